// round 4
// baseline (speedup 1.0000x reference)
#include <cuda_runtime.h>
#include <cstdint>

#define B_  256
#define T_  512
#define I_  64
#define H_  512

#define CLUSTER 8
#define NGROUP  16           // 16 batch groups (clusters)
#define BC      16           // batch rows per cluster
#define NT      128          // threads per CTA

// ---------------- helpers ----------------
__device__ __forceinline__ void ffma2(unsigned long long &d, unsigned long long a, unsigned long long b) {
    asm("fma.rn.f32x2 %0, %1, %2, %0;" : "+l"(d) : "l"(a), "l"(b));
}
__device__ __forceinline__ unsigned long long dup2(float w) {
    unsigned long long r;
    asm("mov.b64 %0, {%1, %1};" : "=l"(r) : "f"(w));
    return r;
}
__device__ __forceinline__ float2 unpack2(unsigned long long v) {
    float2 r;
    asm("mov.b64 {%0, %1}, %2;" : "=f"(r.x), "=f"(r.y) : "l"(v));
    return r;
}
__device__ __forceinline__ float tanh_ap(float x) {
    float y;
    asm("tanh.approx.f32 %0, %1;" : "=f"(y) : "f"(x));
    return y;
}

// ---------------- SMEM layout (floats) ----------------
// W_s   : [512][64]      32768   (W_hh column slice)
// Wx_s  : [64][64]        4096   (W_xh column slice)
// h_s   : [2][512][16]   16384   (double-buffered hidden, [hid][row])
// x_ts  : [2][64][16]     2048   (double-buffered x tile, transposed [i][row])
#define OFF_W   0
#define OFF_WX  (H_ * 64)
#define OFF_H   (OFF_WX + I_ * 64)
#define OFF_X   (OFF_H + 2 * H_ * BC)
#define SMEM_FLOATS (OFF_X + 2 * I_ * BC)   // 55296 floats = 221184 B

// ================= fused kernel =================
__global__ void __launch_bounds__(NT) __cluster_dims__(CLUSTER, 1, 1)
rnn_fused(const float* __restrict__ x,
          const float* __restrict__ Wxh,
          const float* __restrict__ Whh,
          const float* __restrict__ bias,
          const float* __restrict__ fcw,
          const float* __restrict__ fcb,
          float* __restrict__ out) {
    extern __shared__ float sm[];
    float* W_s  = sm + OFF_W;
    float* Wx_s = sm + OFF_WX;
    float* h_s  = sm + OFF_H;
    float* x_ts = sm + OFF_X;

    const int tid  = threadIdx.x;
    const int rank = blockIdx.x % CLUSTER;
    const int bg   = blockIdx.x / CLUSTER;
    const int jbase = rank * 64;
    const int b0 = bg * BC;

    // ---- stage W_hh slice: W_s[k][0..63] = Whh[k][jbase..+63] ----
    for (int i = tid; i < H_ * 16; i += NT) {
        int k = i >> 4, q = i & 15;
        *(float4*)&W_s[k * 64 + q * 4] =
            *(const float4*)&Whh[(size_t)k * H_ + jbase + q * 4];
    }
    // ---- stage W_xh slice: Wx_s[k2][0..63] ----
    for (int i = tid; i < I_ * 16; i += NT) {
        int k = i >> 4, q = i & 15;
        *(float4*)&Wx_s[k * 64 + q * 4] =
            *(const float4*)&Wxh[(size_t)k * H_ + jbase + q * 4];
    }
    // ---- zero h buffer 0 ----
    for (int i = tid; i < H_ * BC / 4; i += NT)
        ((float4*)h_s)[i] = make_float4(0.f, 0.f, 0.f, 0.f);

    // ---- x loader mapping: thread loads row rr, cols [c0,c0+4) and [c0+32,c0+36) ----
    const int rr = tid & 15;
    const int c0 = (tid >> 4) * 4;            // 0..28
    // stage x for t = 0 (transposed into x_ts[0])
    {
        const float* xrow = x + ((size_t)(b0 + rr) * T_ + 0) * I_;
        float4 v0 = *(const float4*)(xrow + c0);
        float4 v1 = *(const float4*)(xrow + c0 + 32);
        x_ts[(c0 + 0) * 16 + rr] = v0.x;  x_ts[(c0 + 1) * 16 + rr] = v0.y;
        x_ts[(c0 + 2) * 16 + rr] = v0.z;  x_ts[(c0 + 3) * 16 + rr] = v0.w;
        x_ts[(c0 + 32) * 16 + rr] = v1.x; x_ts[(c0 + 33) * 16 + rr] = v1.y;
        x_ts[(c0 + 34) * 16 + rr] = v1.z; x_ts[(c0 + 35) * 16 + rr] = v1.w;
    }
    __syncthreads();

    // ---- compute mapping: warp = (rowgroup rg, colgroup cg); thread = 1 col x 8 rows
    const int warp = tid >> 5, lane = tid & 31;
    const int rg = warp & 1, cg = warp >> 1;
    const int jloc  = cg * 32 + lane;
    const int jglob = jbase + jloc;
    const int r0 = rg * 8;
    const float bj = bias[jglob];

    // DSMEM peer addresses for the h push (hoisted)
    uint32_t local_base = (uint32_t)__cvta_generic_to_shared(h_s)
                        + (uint32_t)((jglob * 16 + r0) * 4);
    uint32_t peer_base[CLUSTER];
    #pragma unroll
    for (int c = 0; c < CLUSTER; c++)
        asm("mapa.shared::cluster.u32 %0, %1, %2;"
            : "=r"(peer_base[c]) : "r"(local_base), "r"(c));
    const uint32_t HBUFB = H_ * BC * 4;       // 32 KB per h buffer

    for (int t = 0; t < T_; t++) {
        const int cur = t & 1, nxt = cur ^ 1;
        const float* hb = h_s + cur * (H_ * BC);
        const float* xb = x_ts + cur * (I_ * BC);

        // prefetch x tile for t+1 (hidden under the k-loops)
        float4 pv0, pv1;
        if (t + 1 < T_) {
            const float* xrow = x + ((size_t)(b0 + rr) * T_ + (t + 1)) * I_;
            pv0 = *(const float4*)(xrow + c0);
            pv1 = *(const float4*)(xrow + c0 + 32);
        }

        unsigned long long a0 = 0ull, a1 = 0ull, a2 = 0ull, a3 = 0ull;

        // xh contribution: 64-k2 loop over x_ts
        #pragma unroll 8
        for (int k = 0; k < I_; k++) {
            unsigned long long wd = dup2(Wx_s[k * 64 + jloc]);
            ulonglong2 hA = *(const ulonglong2*)&xb[k * 16 + r0];
            ulonglong2 hB = *(const ulonglong2*)&xb[k * 16 + r0 + 4];
            ffma2(a0, hA.x, wd); ffma2(a1, hA.y, wd);
            ffma2(a2, hB.x, wd); ffma2(a3, hB.y, wd);
        }
        // recurrence: 512-k loop over h_s
        #pragma unroll 8
        for (int k = 0; k < H_; k++) {
            unsigned long long wd = dup2(W_s[k * 64 + jloc]);
            ulonglong2 hA = *(const ulonglong2*)&hb[k * 16 + r0];
            ulonglong2 hB = *(const ulonglong2*)&hb[k * 16 + r0 + 4];
            ffma2(a0, hA.x, wd); ffma2(a1, hA.y, wd);
            ffma2(a2, hB.x, wd); ffma2(a3, hB.y, wd);
        }

        float2 q0 = unpack2(a0), q1 = unpack2(a1);
        float2 q2 = unpack2(a2), q3 = unpack2(a3);
        float o0 = tanh_ap(q0.x + bj), o1 = tanh_ap(q0.y + bj);
        float o2 = tanh_ap(q1.x + bj), o3 = tanh_ap(q1.y + bj);
        float o4 = tanh_ap(q2.x + bj), o5 = tanh_ap(q2.y + bj);
        float o6 = tanh_ap(q3.x + bj), o7 = tanh_ap(q3.y + bj);

        // write the transposed x tile for t+1
        if (t + 1 < T_) {
            float* xn = x_ts + nxt * (I_ * BC);
            xn[(c0 + 0) * 16 + rr] = pv0.x;  xn[(c0 + 1) * 16 + rr] = pv0.y;
            xn[(c0 + 2) * 16 + rr] = pv0.z;  xn[(c0 + 3) * 16 + rr] = pv0.w;
            xn[(c0 + 32) * 16 + rr] = pv1.x; xn[(c0 + 33) * 16 + rr] = pv1.y;
            xn[(c0 + 34) * 16 + rr] = pv1.z; xn[(c0 + 35) * 16 + rr] = pv1.w;
        }

        // push my 8 h values into every cluster CTA's next buffer
        const uint32_t woff = (uint32_t)nxt * HBUFB;
        #pragma unroll
        for (int c = 0; c < CLUSTER; c++) {
            asm volatile("st.shared::cluster.v4.f32 [%0], {%1,%2,%3,%4};"
                         :: "r"(peer_base[c] + woff),
                            "f"(o0), "f"(o1), "f"(o2), "f"(o3) : "memory");
            asm volatile("st.shared::cluster.v4.f32 [%0], {%1,%2,%3,%4};"
                         :: "r"(peer_base[c] + woff + 16),
                            "f"(o4), "f"(o5), "f"(o6), "f"(o7) : "memory");
        }

        // release my stores / acquire peers' stores (also orders x_ts staging)
        asm volatile("barrier.cluster.arrive.aligned;" ::: "memory");
        asm volatile("barrier.cluster.wait.aligned;" ::: "memory");
    }

    // ---- epilogue: rank 0 computes out = h_final @ fc_w^T + fc_b for its 16 rows
    if (rank == 0) {
        const float* hf = h_s;                 // final h is in buffer (T_&1)=0
        const int r  = tid >> 3;               // 0..15
        const int sg = tid & 7;                // 0..7 -> 64-wide j segment
        float p = 0.f;
        #pragma unroll 8
        for (int j = sg * 64; j < sg * 64 + 64; j++)
            p = fmaf(hf[j * 16 + r], fcw[j], p);
        p += __shfl_xor_sync(0xffffffffu, p, 4);
        p += __shfl_xor_sync(0xffffffffu, p, 2);
        p += __shfl_xor_sync(0xffffffffu, p, 1);
        if (sg == 0) out[b0 + r] = p + fcb[0];
    }
}

// ================= launch =================
extern "C" void kernel_launch(void* const* d_in, const int* in_sizes, int n_in,
                              void* d_out, int out_size) {
    const float* x    = (const float*)d_in[0];
    const float* Wxh  = (const float*)d_in[1];
    const float* Whh  = (const float*)d_in[2];
    const float* bias = (const float*)d_in[3];
    const float* fcw  = (const float*)d_in[4];
    const float* fcb  = (const float*)d_in[5];
    float* out = (float*)d_out;

    const int smem = SMEM_FLOATS * 4;          // 221184 B
    cudaFuncSetAttribute(rnn_fused, cudaFuncAttributeMaxDynamicSharedMemorySize, smem);
    rnn_fused<<<NGROUP * CLUSTER, NT, smem>>>(x, Wxh, Whh, bias, fcw, fcb, out);
}

// round 5
// speedup vs baseline: 1.3734x; 1.3734x over previous
#include <cuda_runtime.h>
#include <cstdint>

#define B_  256
#define T_  512
#define I_  64
#define H_  512

#define CLUSTER 8
#define NGROUP  16           // 16 batch groups (clusters)
#define BC      16           // batch rows per cluster
#define NT      512          // threads per CTA (16 warps, 4 per SMSP)

// ---------------- helpers ----------------
__device__ __forceinline__ void ffma2(unsigned long long &d, unsigned long long a, unsigned long long b) {
    asm("fma.rn.f32x2 %0, %1, %2, %0;" : "+l"(d) : "l"(a), "l"(b));
}
__device__ __forceinline__ unsigned long long addf2(unsigned long long a, unsigned long long b) {
    unsigned long long d;
    asm("add.rn.f32x2 %0, %1, %2;" : "=l"(d) : "l"(a), "l"(b));
    return d;
}
__device__ __forceinline__ unsigned long long dup2(float w) {
    unsigned long long r;
    asm("mov.b64 %0, {%1, %1};" : "=l"(r) : "f"(w));
    return r;
}
__device__ __forceinline__ float2 unpack2(unsigned long long v) {
    float2 r;
    asm("mov.b64 {%0, %1}, %2;" : "=f"(r.x), "=f"(r.y) : "l"(v));
    return r;
}
__device__ __forceinline__ float tanh_ap(float x) {
    float y;
    asm("tanh.approx.f32 %0, %1;" : "=f"(y) : "f"(x));
    return y;
}

// ---------------- SMEM layout (floats) ----------------
// W_s  : [512][64]     32768
// Wx_s : [64][64]       4096
// h_s  : [2][512][16]  16384
// x_ts : [2][64][16]    2048
// red  : [8][128] ull   2048 floats (8 KB)
#define OFF_W   0
#define OFF_WX  (H_ * 64)
#define OFF_H   (OFF_WX + I_ * 64)
#define OFF_X   (OFF_H + 2 * H_ * BC)
#define OFF_RED (OFF_X + 2 * I_ * BC)
#define SMEM_FLOATS (OFF_RED + 2048)      // 57344 floats = 229376 B

// ================= fused kernel =================
__global__ void __launch_bounds__(NT) __cluster_dims__(CLUSTER, 1, 1)
rnn_fused(const float* __restrict__ x,
          const float* __restrict__ Wxh,
          const float* __restrict__ Whh,
          const float* __restrict__ bias,
          const float* __restrict__ fcw,
          const float* __restrict__ fcb,
          float* __restrict__ out) {
    extern __shared__ float sm[];
    float* W_s  = sm + OFF_W;
    float* Wx_s = sm + OFF_WX;
    float* h_s  = sm + OFF_H;
    float* x_ts = sm + OFF_X;
    unsigned long long* red = (unsigned long long*)(sm + OFF_RED);

    const int tid  = threadIdx.x;
    const int rank = blockIdx.x % CLUSTER;
    const int bg   = blockIdx.x / CLUSTER;
    const int jbase = rank * 64;
    const int b0 = bg * BC;

    // ---- stage W_hh slice: W_s[k][0..63] = Whh[k][jbase..+63] ----
    for (int i = tid; i < H_ * 16; i += NT) {
        int k = i >> 4, q = i & 15;
        *(float4*)&W_s[k * 64 + q * 4] =
            *(const float4*)&Whh[(size_t)k * H_ + jbase + q * 4];
    }
    // ---- stage W_xh slice ----
    for (int i = tid; i < I_ * 16; i += NT) {
        int k = i >> 4, q = i & 15;
        *(float4*)&Wx_s[k * 64 + q * 4] =
            *(const float4*)&Wxh[(size_t)k * H_ + jbase + q * 4];
    }
    // ---- zero h buffer 0 ----
    for (int i = tid; i < H_ * BC / 4; i += NT)
        ((float4*)h_s)[i] = make_float4(0.f, 0.f, 0.f, 0.f);

    // ---- x loader mapping: thread -> (row rr, float2 col c2) ----
    const int c2 = tid & 31;           // float2 index 0..31
    const int rr = tid >> 5;           // 0..15
    {   // stage x for t = 0 (transposed)
        float2 v = *(const float2*)(x + ((size_t)(b0 + rr) * T_ + 0) * I_ + c2 * 2);
        x_ts[(c2 * 2 + 0) * 16 + rr] = v.x;
        x_ts[(c2 * 2 + 1) * 16 + rr] = v.y;
    }
    __syncthreads();

    // ---- compute mapping ----
    const int warp = tid >> 5, lane = tid & 31;
    const int kq = warp & 3;           // k-quarter 0..3
    const int wq = warp >> 2;          // 0..3
    const int rg = wq & 1, cg = wq >> 1;
    const int jloc  = cg * 32 + lane;
    const int jglob = jbase + jloc;
    const int r0 = rg * 8;
    const int kbase  = kq * 128;       // H-loop slice
    const int kxbase = kq * 16;        // I-loop slice
    const int slot = wq * 32 + lane;   // 0..127 reduction slot
    const float bj = bias[jglob];

    // DSMEM peer addresses (used by kq==0 threads)
    uint32_t local_base = (uint32_t)__cvta_generic_to_shared(h_s)
                        + (uint32_t)((jglob * 16 + r0) * 4);
    uint32_t peer_base[CLUSTER];
    #pragma unroll
    for (int c = 0; c < CLUSTER; c++)
        asm("mapa.shared::cluster.u32 %0, %1, %2;"
            : "=r"(peer_base[c]) : "r"(local_base), "r"(c));
    const uint32_t HBUFB = H_ * BC * 4;       // 32 KB per h buffer

    for (int t = 0; t < T_; t++) {
        const int cur = t & 1, nxt = cur ^ 1;
        const float* hb = h_s + cur * (H_ * BC);
        const float* xb = x_ts + cur * (I_ * BC);

        // prefetch x tile for t+1
        float2 pv;
        if (t + 1 < T_)
            pv = *(const float2*)(x + ((size_t)(b0 + rr) * T_ + (t + 1)) * I_ + c2 * 2);

        unsigned long long a0 = 0ull, a1 = 0ull, a2 = 0ull, a3 = 0ull;

        // xh contribution: 16 i's of the I=64 loop
        #pragma unroll
        for (int i = 0; i < 16; i++) {
            int k = kxbase + i;
            unsigned long long wd = dup2(Wx_s[k * 64 + jloc]);
            ulonglong2 hA = *(const ulonglong2*)&xb[k * 16 + r0];
            ulonglong2 hB = *(const ulonglong2*)&xb[k * 16 + r0 + 4];
            ffma2(a0, hA.x, wd); ffma2(a1, hA.y, wd);
            ffma2(a2, hB.x, wd); ffma2(a3, hB.y, wd);
        }
        // recurrence: 128 k's of the H=512 loop
        #pragma unroll 8
        for (int i = 0; i < 128; i++) {
            int k = kbase + i;
            unsigned long long wd = dup2(W_s[k * 64 + jloc]);
            ulonglong2 hA = *(const ulonglong2*)&hb[k * 16 + r0];
            ulonglong2 hB = *(const ulonglong2*)&hb[k * 16 + r0 + 4];
            ffma2(a0, hA.x, wd); ffma2(a1, hA.y, wd);
            ffma2(a2, hB.x, wd); ffma2(a3, hB.y, wd);
        }

        // stage x(t+1) into the nxt buffer (nxt not read until after cluster barrier)
        if (t + 1 < T_) {
            float* xn = x_ts + nxt * (I_ * BC);
            xn[(c2 * 2 + 0) * 16 + rr] = pv.x;
            xn[(c2 * 2 + 1) * 16 + rr] = pv.y;
        }

        // ---- two-round k-reduction in SMEM ----
        // round 1: kq2 -> cols 0..3, kq3 -> cols 4..7
        if (kq == 2) {
            red[0 * 128 + slot] = a0; red[1 * 128 + slot] = a1;
            red[2 * 128 + slot] = a2; red[3 * 128 + slot] = a3;
        } else if (kq == 3) {
            red[4 * 128 + slot] = a0; red[5 * 128 + slot] = a1;
            red[6 * 128 + slot] = a2; red[7 * 128 + slot] = a3;
        }
        __syncthreads();
        if (kq == 0) {
            a0 = addf2(a0, red[0 * 128 + slot]); a1 = addf2(a1, red[1 * 128 + slot]);
            a2 = addf2(a2, red[2 * 128 + slot]); a3 = addf2(a3, red[3 * 128 + slot]);
        } else if (kq == 1) {
            a0 = addf2(a0, red[4 * 128 + slot]); a1 = addf2(a1, red[5 * 128 + slot]);
            a2 = addf2(a2, red[6 * 128 + slot]); a3 = addf2(a3, red[7 * 128 + slot]);
        }
        __syncthreads();
        // round 2: kq1 -> cols 0..3
        if (kq == 1) {
            red[0 * 128 + slot] = a0; red[1 * 128 + slot] = a1;
            red[2 * 128 + slot] = a2; red[3 * 128 + slot] = a3;
        }
        __syncthreads();

        if (kq == 0) {
            a0 = addf2(a0, red[0 * 128 + slot]); a1 = addf2(a1, red[1 * 128 + slot]);
            a2 = addf2(a2, red[2 * 128 + slot]); a3 = addf2(a3, red[3 * 128 + slot]);

            float2 q0 = unpack2(a0), q1 = unpack2(a1);
            float2 q2 = unpack2(a2), q3 = unpack2(a3);
            float o0 = tanh_ap(q0.x + bj), o1 = tanh_ap(q0.y + bj);
            float o2 = tanh_ap(q1.x + bj), o3 = tanh_ap(q1.y + bj);
            float o4 = tanh_ap(q2.x + bj), o5 = tanh_ap(q2.y + bj);
            float o6 = tanh_ap(q3.x + bj), o7 = tanh_ap(q3.y + bj);

            const uint32_t woff = (uint32_t)nxt * HBUFB;
            #pragma unroll
            for (int c = 0; c < CLUSTER; c++) {
                asm volatile("st.shared::cluster.v4.f32 [%0], {%1,%2,%3,%4};"
                             :: "r"(peer_base[c] + woff),
                                "f"(o0), "f"(o1), "f"(o2), "f"(o3) : "memory");
                asm volatile("st.shared::cluster.v4.f32 [%0], {%1,%2,%3,%4};"
                             :: "r"(peer_base[c] + woff + 16),
                                "f"(o4), "f"(o5), "f"(o6), "f"(o7) : "memory");
            }
        }

        // release my stores / acquire peers' stores
        asm volatile("barrier.cluster.arrive.aligned;" ::: "memory");
        asm volatile("barrier.cluster.wait.aligned;" ::: "memory");
    }

    // ---- epilogue: rank 0 computes out = h_final @ fc_w^T + fc_b ----
    if (rank == 0 && tid < 128) {
        const float* hf = h_s;                 // T_ even -> final h in buffer 0
        const int r  = tid >> 3;               // 0..15
        const int sg = tid & 7;                // 0..7
        float p = 0.f;
        #pragma unroll 8
        for (int j = sg * 64; j < sg * 64 + 64; j++)
            p = fmaf(hf[j * 16 + r], fcw[j], p);
        p += __shfl_xor_sync(0xffffffffu, p, 4);
        p += __shfl_xor_sync(0xffffffffu, p, 2);
        p += __shfl_xor_sync(0xffffffffu, p, 1);
        if (sg == 0) out[b0 + r] = p + fcb[0];
    }
}

// ================= launch =================
extern "C" void kernel_launch(void* const* d_in, const int* in_sizes, int n_in,
                              void* d_out, int out_size) {
    const float* x    = (const float*)d_in[0];
    const float* Wxh  = (const float*)d_in[1];
    const float* Whh  = (const float*)d_in[2];
    const float* bias = (const float*)d_in[3];
    const float* fcw  = (const float*)d_in[4];
    const float* fcb  = (const float*)d_in[5];
    float* out = (float*)d_out;

    const int smem = SMEM_FLOATS * 4;          // 229376 B
    cudaFuncSetAttribute(rnn_fused, cudaFuncAttributeMaxDynamicSharedMemorySize, smem);
    rnn_fused<<<NGROUP * CLUSTER, NT, smem>>>(x, Wxh, Whh, bias, fcw, fcb, out);
}

// round 6
// speedup vs baseline: 1.6178x; 1.1780x over previous
#include <cuda_runtime.h>
#include <cstdint>

#define B_  256
#define T_  512
#define I_  64
#define H_  512

#define CLUSTER 8
#define NGROUP  16           // 16 batch groups (clusters)
#define BC      16           // batch rows per cluster
#define NT      512          // threads per CTA (16 warps)

#define SLICE_BYTES 4096     // 64 cols x 16 rows x 4B
#define EXPECT_BYTES (7 * SLICE_BYTES)   // 7 remote slices per step

// ---------------- helpers ----------------
__device__ __forceinline__ void ffma2(unsigned long long &d, unsigned long long a, unsigned long long b) {
    asm("fma.rn.f32x2 %0, %1, %2, %0;" : "+l"(d) : "l"(a), "l"(b));
}
__device__ __forceinline__ unsigned long long addf2(unsigned long long a, unsigned long long b) {
    unsigned long long d;
    asm("add.rn.f32x2 %0, %1, %2;" : "=l"(d) : "l"(a), "l"(b));
    return d;
}
__device__ __forceinline__ unsigned long long dup2(float w) {
    unsigned long long r;
    asm("mov.b64 %0, {%1, %1};" : "=l"(r) : "f"(w));
    return r;
}
__device__ __forceinline__ float2 unpack2(unsigned long long v) {
    float2 r;
    asm("mov.b64 {%0, %1}, %2;" : "=f"(r.x), "=f"(r.y) : "l"(v));
    return r;
}
__device__ __forceinline__ float tanh_ap(float x) {
    float y;
    asm("tanh.approx.f32 %0, %1;" : "=f"(y) : "f"(x));
    return y;
}
__device__ __forceinline__ void mbar_wait(uint32_t mbar, uint32_t parity) {
    asm volatile(
        "{\n\t.reg .pred P;\n\t"
        "WL_%=:\n\t"
        "mbarrier.try_wait.parity.acquire.cta.shared::cta.b64 P, [%0], %1, 0x989680;\n\t"
        "@P bra.uni WD_%=;\n\t"
        "bra.uni WL_%=;\n\t"
        "WD_%=:\n\t}"
        :: "r"(mbar), "r"(parity) : "memory");
}

// ---------------- SMEM layout (floats) ----------------
#define OFF_W   0                          // [512][64]  W_hh slice
#define OFF_WX  (H_ * 64)                  // [64][64]   W_xh slice
#define OFF_H   (OFF_WX + I_ * 64)         // [2][512][16] hidden, double-buffered
#define OFF_X   (OFF_H + 2 * H_ * BC)      // [2][64][16]  x tile, double-buffered
#define OFF_RED (OFF_X + 2 * I_ * BC)      // [8][128] ull reduction
#define OFF_MB  (OFF_RED + 2048)           // 2 mbarriers (16B)
#define SMEM_FLOATS (OFF_MB + 16)          // 57360 floats = 229440 B

// ================= fused kernel =================
__global__ void __launch_bounds__(NT) __cluster_dims__(CLUSTER, 1, 1)
rnn_fused(const float* __restrict__ x,
          const float* __restrict__ Wxh,
          const float* __restrict__ Whh,
          const float* __restrict__ bias,
          const float* __restrict__ fcw,
          const float* __restrict__ fcb,
          float* __restrict__ out) {
    extern __shared__ float sm[];
    float* W_s  = sm + OFF_W;
    float* Wx_s = sm + OFF_WX;
    float* h_s  = sm + OFF_H;
    float* x_ts = sm + OFF_X;
    unsigned long long* red = (unsigned long long*)(sm + OFF_RED);

    const uint32_t smem_u32 = (uint32_t)__cvta_generic_to_shared(sm);
    const uint32_t mb0 = smem_u32 + OFF_MB * 4;
    const uint32_t mb1 = mb0 + 8;

    const int tid  = threadIdx.x;
    const int rank = blockIdx.x % CLUSTER;
    const int bg   = blockIdx.x / CLUSTER;
    const int jbase = rank * 64;
    const int b0 = bg * BC;

    // ---- init mbarriers (count 1) and pre-arm first two uses ----
    if (tid == 0) {
        asm volatile("mbarrier.init.shared.b64 [%0], 1;" :: "r"(mb0) : "memory");
        asm volatile("mbarrier.init.shared.b64 [%0], 1;" :: "r"(mb1) : "memory");
        asm volatile("mbarrier.arrive.expect_tx.shared.b64 _, [%0], %1;"
                     :: "r"(mb0), "r"(EXPECT_BYTES) : "memory");
        asm volatile("mbarrier.arrive.expect_tx.shared.b64 _, [%0], %1;"
                     :: "r"(mb1), "r"(EXPECT_BYTES) : "memory");
    }

    // ---- stage W_hh slice ----
    for (int i = tid; i < H_ * 16; i += NT) {
        int k = i >> 4, q = i & 15;
        *(float4*)&W_s[k * 64 + q * 4] =
            *(const float4*)&Whh[(size_t)k * H_ + jbase + q * 4];
    }
    // ---- stage W_xh slice ----
    for (int i = tid; i < I_ * 16; i += NT) {
        int k = i >> 4, q = i & 15;
        *(float4*)&Wx_s[k * 64 + q * 4] =
            *(const float4*)&Wxh[(size_t)k * H_ + jbase + q * 4];
    }
    // ---- zero h buffer 0 ----
    for (int i = tid; i < H_ * BC / 4; i += NT)
        ((float4*)h_s)[i] = make_float4(0.f, 0.f, 0.f, 0.f);

    // ---- x loader mapping ----
    const int c2 = tid & 31;
    const int rr = tid >> 5;
    {
        float2 v = *(const float2*)(x + ((size_t)(b0 + rr) * T_ + 0) * I_ + c2 * 2);
        x_ts[(c2 * 2 + 0) * 16 + rr] = v.x;
        x_ts[(c2 * 2 + 1) * 16 + rr] = v.y;
    }
    __syncthreads();
    // cluster-wide: peers' mbarriers + SMEM ready before any copies fly
    asm volatile("barrier.cluster.arrive.aligned;" ::: "memory");
    asm volatile("barrier.cluster.wait.aligned;" ::: "memory");

    // ---- compute mapping ----
    const int warp = tid >> 5, lane = tid & 31;
    const int kq = warp & 3;
    const int wq = warp >> 2;
    const int rg = wq & 1, cg = wq >> 1;
    const int jloc  = cg * 32 + lane;
    const int jglob = jbase + jloc;
    const int r0 = rg * 8;
    const int kbase  = kq * 128;
    const int kxbase = kq * 16;
    const int slot = wq * 32 + lane;
    const float bj = bias[jglob];

    // ---- copy descriptors (warp 0, lanes 0..6): dest rank, dst slice, remote mbar
    const uint32_t HBUFB = H_ * BC * 4;                     // 32 KB per h buffer
    const uint32_t slice_local = smem_u32 + OFF_H * 4 + (uint32_t)jbase * 64;
    uint32_t dst_base = 0, rmb_base = 0;
    if (warp == 0 && lane < 7) {
        int c = (rank + 1 + lane) & 7;                      // skip self
        asm("mapa.shared::cluster.u32 %0, %1, %2;" : "=r"(dst_base) : "r"(slice_local), "r"(c));
        asm("mapa.shared::cluster.u32 %0, %1, %2;" : "=r"(rmb_base) : "r"(mb0), "r"(c));
    }

    for (int t = 0; t < T_; t++) {
        const int cur = t & 1, nxt = cur ^ 1;

        // ---- wait for this step's h (remote slices), re-arm for t+2 ----
        if (t >= 1) {
            const uint32_t mb = cur ? mb1 : mb0;
            mbar_wait(mb, (uint32_t)(((t - 1) >> 1) & 1));
            if (tid == 0)
                asm volatile("mbarrier.arrive.expect_tx.shared.b64 _, [%0], %1;"
                             :: "r"(mb), "r"(EXPECT_BYTES) : "memory");
        }
        __syncthreads();   // order prev step's local-slice STS for all readers

        const float* hb = h_s + cur * (H_ * BC);
        const float* xb = x_ts + cur * (I_ * BC);

        // prefetch x tile for t+1
        float2 pv;
        if (t + 1 < T_)
            pv = *(const float2*)(x + ((size_t)(b0 + rr) * T_ + (t + 1)) * I_ + c2 * 2);

        unsigned long long a0 = 0ull, a1 = 0ull, a2 = 0ull, a3 = 0ull;

        #pragma unroll
        for (int i = 0; i < 16; i++) {
            int k = kxbase + i;
            unsigned long long wd = dup2(Wx_s[k * 64 + jloc]);
            ulonglong2 hA = *(const ulonglong2*)&xb[k * 16 + r0];
            ulonglong2 hB = *(const ulonglong2*)&xb[k * 16 + r0 + 4];
            ffma2(a0, hA.x, wd); ffma2(a1, hA.y, wd);
            ffma2(a2, hB.x, wd); ffma2(a3, hB.y, wd);
        }
        #pragma unroll 8
        for (int i = 0; i < 128; i++) {
            int k = kbase + i;
            unsigned long long wd = dup2(W_s[k * 64 + jloc]);
            ulonglong2 hA = *(const ulonglong2*)&hb[k * 16 + r0];
            ulonglong2 hB = *(const ulonglong2*)&hb[k * 16 + r0 + 4];
            ffma2(a0, hA.x, wd); ffma2(a1, hA.y, wd);
            ffma2(a2, hB.x, wd); ffma2(a3, hB.y, wd);
        }

        // stage x(t+1) (read next step after top __syncthreads)
        if (t + 1 < T_) {
            float* xn = x_ts + nxt * (I_ * BC);
            xn[(c2 * 2 + 0) * 16 + rr] = pv.x;
            xn[(c2 * 2 + 1) * 16 + rr] = pv.y;
        }

        // ---- two-round k-reduction ----
        if (kq == 2) {
            red[0 * 128 + slot] = a0; red[1 * 128 + slot] = a1;
            red[2 * 128 + slot] = a2; red[3 * 128 + slot] = a3;
        } else if (kq == 3) {
            red[4 * 128 + slot] = a0; red[5 * 128 + slot] = a1;
            red[6 * 128 + slot] = a2; red[7 * 128 + slot] = a3;
        }
        __syncthreads();
        if (kq == 0) {
            a0 = addf2(a0, red[0 * 128 + slot]); a1 = addf2(a1, red[1 * 128 + slot]);
            a2 = addf2(a2, red[2 * 128 + slot]); a3 = addf2(a3, red[3 * 128 + slot]);
        } else if (kq == 1) {
            a0 = addf2(a0, red[4 * 128 + slot]); a1 = addf2(a1, red[5 * 128 + slot]);
            a2 = addf2(a2, red[6 * 128 + slot]); a3 = addf2(a3, red[7 * 128 + slot]);
        }
        __syncthreads();
        if (kq == 1) {
            red[0 * 128 + slot] = a0; red[1 * 128 + slot] = a1;
            red[2 * 128 + slot] = a2; red[3 * 128 + slot] = a3;
        }
        __syncthreads();

        if (kq == 0) {
            a0 = addf2(a0, red[0 * 128 + slot]); a1 = addf2(a1, red[1 * 128 + slot]);
            a2 = addf2(a2, red[2 * 128 + slot]); a3 = addf2(a3, red[3 * 128 + slot]);

            float2 q0 = unpack2(a0), q1 = unpack2(a1);
            float2 q2 = unpack2(a2), q3 = unpack2(a3);
            float o0 = tanh_ap(q0.x + bj), o1 = tanh_ap(q0.y + bj);
            float o2 = tanh_ap(q1.x + bj), o3 = tanh_ap(q1.y + bj);
            float o4 = tanh_ap(q2.x + bj), o5 = tanh_ap(q2.y + bj);
            float o6 = tanh_ap(q3.x + bj), o7 = tanh_ap(q3.y + bj);

            // write local slice (also the bulk-copy source)
            float* dstl = h_s + nxt * (H_ * BC) + (jglob * 16 + r0);
            *(float4*)(dstl)     = make_float4(o0, o1, o2, o3);
            *(float4*)(dstl + 4) = make_float4(o4, o5, o6, o7);

            // sync the 4 kq0 warps, then 7 threads push slices to peers
            asm volatile("bar.sync 1, 128;" ::: "memory");
            if (warp == 0 && lane < 7) {
                asm volatile("fence.proxy.async.shared::cta;" ::: "memory");
                const uint32_t woff = (uint32_t)nxt * HBUFB;
                const uint32_t src  = slice_local + woff;
                const uint32_t rmb  = rmb_base + (uint32_t)nxt * 8;
                asm volatile(
                    "cp.async.bulk.shared::cluster.shared::cta.mbarrier::complete_tx::bytes "
                    "[%0], [%1], %2, [%3];"
                    :: "r"(dst_base + woff), "r"(src), "r"(SLICE_BYTES), "r"(rmb)
                    : "memory");
            }
        }
    }

    // ---- epilogue: rank 0 computes out = h_final @ fc_w^T + fc_b ----
    if (rank == 0)
        mbar_wait(mb0, (uint32_t)(((T_ - 1 + 1 - 1) >> 1) & 1));   // t=512 use -> parity 1
    __syncthreads();   // also orders kq0's final local-slice writes
    if (rank == 0 && tid < 128) {
        const float* hf = h_s;                 // final h in buffer 0
        const int r  = tid >> 3;
        const int sg = tid & 7;
        float p = 0.f;
        #pragma unroll 8
        for (int j = sg * 64; j < sg * 64 + 64; j++)
            p = fmaf(hf[j * 16 + r], fcw[j], p);
        p += __shfl_xor_sync(0xffffffffu, p, 4);
        p += __shfl_xor_sync(0xffffffffu, p, 2);
        p += __shfl_xor_sync(0xffffffffu, p, 1);
        if (sg == 0) out[b0 + r] = p + fcb[0];
    }
    // keep the cluster alive until all in-flight copies land
    asm volatile("barrier.cluster.arrive.aligned;" ::: "memory");
    asm volatile("barrier.cluster.wait.aligned;" ::: "memory");
}

// ================= launch =================
extern "C" void kernel_launch(void* const* d_in, const int* in_sizes, int n_in,
                              void* d_out, int out_size) {
    const float* x    = (const float*)d_in[0];
    const float* Wxh  = (const float*)d_in[1];
    const float* Whh  = (const float*)d_in[2];
    const float* bias = (const float*)d_in[3];
    const float* fcw  = (const float*)d_in[4];
    const float* fcb  = (const float*)d_in[5];
    float* out = (float*)d_out;

    const int smem = SMEM_FLOATS * 4;          // 229440 B
    cudaFuncSetAttribute(rnn_fused, cudaFuncAttributeMaxDynamicSharedMemorySize, smem);
    rnn_fused<<<NGROUP * CLUSTER, NT, smem>>>(x, Wxh, Whh, bias, fcw, fcb, out);
}

// round 7
// speedup vs baseline: 1.6253x; 1.0046x over previous
#include <cuda_runtime.h>
#include <cstdint>

#define B_  256
#define T_  512
#define I_  64
#define H_  512

#define CLUSTER 8
#define NGROUP  16           // 16 batch groups (clusters)
#define BC      16           // batch rows per cluster
#define NT      512          // threads per CTA (16 warps)

#define SLICE_BYTES 4096     // 64 cols x 16 rows x 4B
#define EXPECT_BYTES (7 * SLICE_BYTES)   // 7 remote slices per step

// ---------------- helpers ----------------
__device__ __forceinline__ void ffma2(unsigned long long &d, unsigned long long a, unsigned long long b) {
    asm("fma.rn.f32x2 %0, %1, %2, %0;" : "+l"(d) : "l"(a), "l"(b));
}
__device__ __forceinline__ unsigned long long addf2(unsigned long long a, unsigned long long b) {
    unsigned long long d;
    asm("add.rn.f32x2 %0, %1, %2;" : "=l"(d) : "l"(a), "l"(b));
    return d;
}
__device__ __forceinline__ unsigned long long dup2(float w) {
    unsigned long long r;
    asm("mov.b64 %0, {%1, %1};" : "=l"(r) : "f"(w));
    return r;
}
__device__ __forceinline__ float2 unpack2(unsigned long long v) {
    float2 r;
    asm("mov.b64 {%0, %1}, %2;" : "=f"(r.x), "=f"(r.y) : "l"(v));
    return r;
}
__device__ __forceinline__ float tanh_ap(float x) {
    float y;
    asm("tanh.approx.f32 %0, %1;" : "=f"(y) : "f"(x));
    return y;
}
__device__ __forceinline__ void mbar_wait(uint32_t mbar, uint32_t parity) {
    asm volatile(
        "{\n\t.reg .pred P;\n\t"
        "WL_%=:\n\t"
        "mbarrier.try_wait.parity.acquire.cta.shared::cta.b64 P, [%0], %1, 0x989680;\n\t"
        "@P bra.uni WD_%=;\n\t"
        "bra.uni WL_%=;\n\t"
        "WD_%=:\n\t}"
        :: "r"(mbar), "r"(parity) : "memory");
}

// ---------------- SMEM layout (floats) ----------------
#define OFF_W   0                          // [512][64]  W_hh slice
#define OFF_WX  (H_ * 64)                  // [64][64]   W_xh slice
#define OFF_H   (OFF_WX + I_ * 64)         // [2][512][16] hidden, double-buffered
#define OFF_X   (OFF_H + 2 * H_ * BC)      // [2][64][16]  x tile, double-buffered
#define OFF_RED (OFF_X + 2 * I_ * BC)      // [8][128] ull reduction
#define OFF_MB  (OFF_RED + 2048)           // 2 mbarriers (16B)
#define SMEM_FLOATS (OFF_MB + 16)          // 57360 floats = 229440 B

// ================= fused kernel =================
__global__ void __launch_bounds__(NT) __cluster_dims__(CLUSTER, 1, 1)
rnn_fused(const float* __restrict__ x,
          const float* __restrict__ Wxh,
          const float* __restrict__ Whh,
          const float* __restrict__ bias,
          const float* __restrict__ fcw,
          const float* __restrict__ fcb,
          float* __restrict__ out) {
    extern __shared__ float sm[];
    float* W_s  = sm + OFF_W;
    float* Wx_s = sm + OFF_WX;
    float* h_s  = sm + OFF_H;
    float* x_ts = sm + OFF_X;
    unsigned long long* red = (unsigned long long*)(sm + OFF_RED);

    const uint32_t smem_u32 = (uint32_t)__cvta_generic_to_shared(sm);
    const uint32_t mb0 = smem_u32 + OFF_MB * 4;
    const uint32_t mb1 = mb0 + 8;

    const int tid  = threadIdx.x;
    const int rank = blockIdx.x % CLUSTER;
    const int bg   = blockIdx.x / CLUSTER;
    const int jbase = rank * 64;
    const int b0 = bg * BC;

    // ---- init mbarriers (count 1) and pre-arm first two uses ----
    if (tid == 0) {
        asm volatile("mbarrier.init.shared.b64 [%0], 1;" :: "r"(mb0) : "memory");
        asm volatile("mbarrier.init.shared.b64 [%0], 1;" :: "r"(mb1) : "memory");
        asm volatile("mbarrier.arrive.expect_tx.shared.b64 _, [%0], %1;"
                     :: "r"(mb0), "r"(EXPECT_BYTES) : "memory");
        asm volatile("mbarrier.arrive.expect_tx.shared.b64 _, [%0], %1;"
                     :: "r"(mb1), "r"(EXPECT_BYTES) : "memory");
    }

    // ---- stage W_hh slice ----
    for (int i = tid; i < H_ * 16; i += NT) {
        int k = i >> 4, q = i & 15;
        *(float4*)&W_s[k * 64 + q * 4] =
            *(const float4*)&Whh[(size_t)k * H_ + jbase + q * 4];
    }
    // ---- stage W_xh slice ----
    for (int i = tid; i < I_ * 16; i += NT) {
        int k = i >> 4, q = i & 15;
        *(float4*)&Wx_s[k * 64 + q * 4] =
            *(const float4*)&Wxh[(size_t)k * H_ + jbase + q * 4];
    }
    // ---- zero h buffer 0 ----
    for (int i = tid; i < H_ * BC / 4; i += NT)
        ((float4*)h_s)[i] = make_float4(0.f, 0.f, 0.f, 0.f);

    // ---- x loader mapping ----
    const int c2 = tid & 31;
    const int rr = tid >> 5;
    {
        float2 v = *(const float2*)(x + ((size_t)(b0 + rr) * T_ + 0) * I_ + c2 * 2);
        x_ts[(c2 * 2 + 0) * 16 + rr] = v.x;
        x_ts[(c2 * 2 + 1) * 16 + rr] = v.y;
    }
    __syncthreads();
    // cluster-wide: peers' mbarriers + SMEM ready before any copies fly
    asm volatile("barrier.cluster.arrive.aligned;" ::: "memory");
    asm volatile("barrier.cluster.wait.aligned;" ::: "memory");

    // ---- compute mapping ----
    const int warp = tid >> 5, lane = tid & 31;
    const int kq = warp & 3;
    const int wq = warp >> 2;
    const int rg = wq & 1, cg = wq >> 1;
    const int jloc  = cg * 32 + lane;
    const int jglob = jbase + jloc;
    const int r0 = rg * 8;
    const int kbase  = kq * 128;
    const int kxbase = kq * 16;
    const int slot = wq * 32 + lane;
    const float bj = bias[jglob];

    // ---- copy descriptors (warp 0, lanes 0..6): dest rank, dst slice, remote mbar
    const uint32_t HBUFB = H_ * BC * 4;                     // 32 KB per h buffer
    const uint32_t slice_local = smem_u32 + OFF_H * 4 + (uint32_t)jbase * 64;
    uint32_t dst_base = 0, rmb_base = 0;
    if (warp == 0 && lane < 7) {
        int c = (rank + 1 + lane) & 7;                      // skip self
        asm("mapa.shared::cluster.u32 %0, %1, %2;" : "=r"(dst_base) : "r"(slice_local), "r"(c));
        asm("mapa.shared::cluster.u32 %0, %1, %2;" : "=r"(rmb_base) : "r"(mb0), "r"(c));
    }

    for (int t = 0; t < T_; t++) {
        const int cur = t & 1, nxt = cur ^ 1;

        // ---- wait for this step's h (remote slices), re-arm for t+2 ----
        if (t >= 1) {
            const uint32_t mb = cur ? mb1 : mb0;
            mbar_wait(mb, (uint32_t)(((t - 1) >> 1) & 1));
            if (tid == 0)
                asm volatile("mbarrier.arrive.expect_tx.shared.b64 _, [%0], %1;"
                             :: "r"(mb), "r"(EXPECT_BYTES) : "memory");
        }
        __syncthreads();   // order prev step's local-slice STS for all readers

        const float* hb = h_s + cur * (H_ * BC);
        const float* xb = x_ts + cur * (I_ * BC);

        // prefetch x tile for t+1
        float2 pv;
        if (t + 1 < T_)
            pv = *(const float2*)(x + ((size_t)(b0 + rr) * T_ + (t + 1)) * I_ + c2 * 2);

        unsigned long long a0 = 0ull, a1 = 0ull, a2 = 0ull, a3 = 0ull;

        #pragma unroll
        for (int i = 0; i < 16; i++) {
            int k = kxbase + i;
            unsigned long long wd = dup2(Wx_s[k * 64 + jloc]);
            ulonglong2 hA = *(const ulonglong2*)&xb[k * 16 + r0];
            ulonglong2 hB = *(const ulonglong2*)&xb[k * 16 + r0 + 4];
            ffma2(a0, hA.x, wd); ffma2(a1, hA.y, wd);
            ffma2(a2, hB.x, wd); ffma2(a3, hB.y, wd);
        }
        #pragma unroll 8
        for (int i = 0; i < 128; i++) {
            int k = kbase + i;
            unsigned long long wd = dup2(W_s[k * 64 + jloc]);
            ulonglong2 hA = *(const ulonglong2*)&hb[k * 16 + r0];
            ulonglong2 hB = *(const ulonglong2*)&hb[k * 16 + r0 + 4];
            ffma2(a0, hA.x, wd); ffma2(a1, hA.y, wd);
            ffma2(a2, hB.x, wd); ffma2(a3, hB.y, wd);
        }

        // stage x(t+1) (read next step after top __syncthreads)
        if (t + 1 < T_) {
            float* xn = x_ts + nxt * (I_ * BC);
            xn[(c2 * 2 + 0) * 16 + rr] = pv.x;
            xn[(c2 * 2 + 1) * 16 + rr] = pv.y;
        }

        // ---- two-round k-reduction ----
        if (kq == 2) {
            red[0 * 128 + slot] = a0; red[1 * 128 + slot] = a1;
            red[2 * 128 + slot] = a2; red[3 * 128 + slot] = a3;
        } else if (kq == 3) {
            red[4 * 128 + slot] = a0; red[5 * 128 + slot] = a1;
            red[6 * 128 + slot] = a2; red[7 * 128 + slot] = a3;
        }
        __syncthreads();
        if (kq == 0) {
            a0 = addf2(a0, red[0 * 128 + slot]); a1 = addf2(a1, red[1 * 128 + slot]);
            a2 = addf2(a2, red[2 * 128 + slot]); a3 = addf2(a3, red[3 * 128 + slot]);
        } else if (kq == 1) {
            a0 = addf2(a0, red[4 * 128 + slot]); a1 = addf2(a1, red[5 * 128 + slot]);
            a2 = addf2(a2, red[6 * 128 + slot]); a3 = addf2(a3, red[7 * 128 + slot]);
        }
        __syncthreads();
        if (kq == 1) {
            red[0 * 128 + slot] = a0; red[1 * 128 + slot] = a1;
            red[2 * 128 + slot] = a2; red[3 * 128 + slot] = a3;
        }
        __syncthreads();

        if (kq == 0) {
            a0 = addf2(a0, red[0 * 128 + slot]); a1 = addf2(a1, red[1 * 128 + slot]);
            a2 = addf2(a2, red[2 * 128 + slot]); a3 = addf2(a3, red[3 * 128 + slot]);

            float2 q0 = unpack2(a0), q1 = unpack2(a1);
            float2 q2 = unpack2(a2), q3 = unpack2(a3);
            float o0 = tanh_ap(q0.x + bj), o1 = tanh_ap(q0.y + bj);
            float o2 = tanh_ap(q1.x + bj), o3 = tanh_ap(q1.y + bj);
            float o4 = tanh_ap(q2.x + bj), o5 = tanh_ap(q2.y + bj);
            float o6 = tanh_ap(q3.x + bj), o7 = tanh_ap(q3.y + bj);

            // write local slice (also the bulk-copy source)
            float* dstl = h_s + nxt * (H_ * BC) + (jglob * 16 + r0);
            *(float4*)(dstl)     = make_float4(o0, o1, o2, o3);
            *(float4*)(dstl + 4) = make_float4(o4, o5, o6, o7);

            // sync the 4 kq0 warps, then 7 threads push slices to peers
            asm volatile("bar.sync 1, 128;" ::: "memory");
            if (warp == 0 && lane < 7) {
                asm volatile("fence.proxy.async.shared::cta;" ::: "memory");
                const uint32_t woff = (uint32_t)nxt * HBUFB;
                const uint32_t src  = slice_local + woff;
                const uint32_t rmb  = rmb_base + (uint32_t)nxt * 8;
                asm volatile(
                    "cp.async.bulk.shared::cluster.shared::cta.mbarrier::complete_tx::bytes "
                    "[%0], [%1], %2, [%3];"
                    :: "r"(dst_base + woff), "r"(src), "r"(SLICE_BYTES), "r"(rmb)
                    : "memory");
            }
        }
    }

    // ---- epilogue: rank 0 computes out = h_final @ fc_w^T + fc_b ----
    if (rank == 0)
        mbar_wait(mb0, (uint32_t)(((T_ - 1 + 1 - 1) >> 1) & 1));   // t=512 use -> parity 1
    __syncthreads();   // also orders kq0's final local-slice writes
    if (rank == 0 && tid < 128) {
        const float* hf = h_s;                 // final h in buffer 0
        const int r  = tid >> 3;
        const int sg = tid & 7;
        float p = 0.f;
        #pragma unroll 8
        for (int j = sg * 64; j < sg * 64 + 64; j++)
            p = fmaf(hf[j * 16 + r], fcw[j], p);
        p += __shfl_xor_sync(0xffffffffu, p, 4);
        p += __shfl_xor_sync(0xffffffffu, p, 2);
        p += __shfl_xor_sync(0xffffffffu, p, 1);
        if (sg == 0) out[b0 + r] = p + fcb[0];
    }
    // keep the cluster alive until all in-flight copies land
    asm volatile("barrier.cluster.arrive.aligned;" ::: "memory");
    asm volatile("barrier.cluster.wait.aligned;" ::: "memory");
}

// ================= launch =================
extern "C" void kernel_launch(void* const* d_in, const int* in_sizes, int n_in,
                              void* d_out, int out_size) {
    const float* x    = (const float*)d_in[0];
    const float* Wxh  = (const float*)d_in[1];
    const float* Whh  = (const float*)d_in[2];
    const float* bias = (const float*)d_in[3];
    const float* fcw  = (const float*)d_in[4];
    const float* fcb  = (const float*)d_in[5];
    float* out = (float*)d_out;

    const int smem = SMEM_FLOATS * 4;          // 229440 B
    cudaFuncSetAttribute(rnn_fused, cudaFuncAttributeMaxDynamicSharedMemorySize, smem);
    rnn_fused<<<NGROUP * CLUSTER, NT, smem>>>(x, Wxh, Whh, bias, fcw, fcb, out);
}

// round 9
// speedup vs baseline: 1.9621x; 1.2072x over previous
#include <cuda_runtime.h>
#include <cstdint>

#define B_  256
#define T_  512
#define I_  64
#define H_  512

#define CLUSTER 8
#define NGROUP  16
#define BC      16
#define NT      512

#define SLICE_BYTES 4096
#define EXPECT_BYTES (7 * SLICE_BYTES)

// per-CTA xh scratch: [cta][t][col(64)][row(16)]
__device__ float g_xh[(size_t)(NGROUP * CLUSTER) * T_ * 64 * BC];

typedef unsigned long long ull;

// ---------------- helpers ----------------
__device__ __forceinline__ void ffma2(ull &d, ull a, ull b) {
    asm("fma.rn.f32x2 %0, %1, %2, %0;" : "+l"(d) : "l"(a), "l"(b));
}
__device__ __forceinline__ ull addf2(ull a, ull b) {
    ull d; asm("add.rn.f32x2 %0, %1, %2;" : "=l"(d) : "l"(a), "l"(b)); return d;
}
__device__ __forceinline__ ull dup2(float w) {
    ull r; asm("mov.b64 %0, {%1, %1};" : "=l"(r) : "f"(w)); return r;
}
__device__ __forceinline__ float2 unpack2(ull v) {
    float2 r; asm("mov.b64 {%0, %1}, %2;" : "=f"(r.x), "=f"(r.y) : "l"(v)); return r;
}
__device__ __forceinline__ float tanh_ap(float x) {
    float y; asm("tanh.approx.f32 %0, %1;" : "=f"(y) : "f"(x)); return y;
}
__device__ __forceinline__ void mbar_wait(uint32_t mbar, uint32_t parity) {
    asm volatile(
        "{\n\t.reg .pred P;\n\t"
        "WL_%=:\n\t"
        "mbarrier.try_wait.parity.acquire.cta.shared::cta.b64 P, [%0], %1, 0x989680;\n\t"
        "@P bra.uni WD_%=;\n\t"
        "bra.uni WL_%=;\n\t"
        "WD_%=:\n\t}"
        :: "r"(mbar), "r"(parity) : "memory");
}

// ---------------- SMEM layout (float offsets) ----------------
#define OFF_U   0                       // [512][64] W_hh slice      (131072 B)
#define OFF_Z   (H_ * 64)               // [2][512][16] hidden       ( 65536 B)
#define OFF_RED (OFF_Z + 2 * H_ * BC)   // 4096 fl: red / Wxs alias  ( 16384 B)
#define OFF_MB  (OFF_RED + 4096)
#define SMEM_FLOATS (OFF_MB + 16)       // 53264 fl = 213056 B

__global__ void __launch_bounds__(NT) __cluster_dims__(CLUSTER, 1, 1)
rnn_fused(const float* __restrict__ x,
          const float* __restrict__ Wxh,
          const float* __restrict__ Whh,
          const float* __restrict__ bias,
          const float* __restrict__ fcw,
          const float* __restrict__ fcb,
          float* __restrict__ out) {
    extern __shared__ float sm[];
    float* U   = sm + OFF_U;
    float* z   = sm + OFF_Z;
    ull*  red  = (ull*)(sm + OFF_RED);
    float* Wxs = sm + OFF_RED;          // phase-0 alias (16 KB)
    float* x_ts = sm + OFF_Z;           // phase-0 alias (32 KB of z region)

    const uint32_t smem_u32 = (uint32_t)__cvta_generic_to_shared(sm);
    const uint32_t mb0 = smem_u32 + OFF_MB * 4;
    const uint32_t mb1 = mb0 + 8;

    const int tid  = threadIdx.x;
    const int cta  = blockIdx.x;
    const int rank = cta & 7;
    const int bg   = cta >> 3;
    const int jbase = rank * 64;
    const int b0 = bg * BC;
    const int wid = tid >> 5, lane = tid & 31;

    if (tid == 0) {
        asm volatile("mbarrier.init.shared.b64 [%0], 1;" :: "r"(mb0) : "memory");
        asm volatile("mbarrier.init.shared.b64 [%0], 1;" :: "r"(mb1) : "memory");
        asm volatile("mbarrier.arrive.expect_tx.shared.b64 _, [%0], %1;"
                     :: "r"(mb0), "r"(EXPECT_BYTES) : "memory");
        asm volatile("mbarrier.arrive.expect_tx.shared.b64 _, [%0], %1;"
                     :: "r"(mb1), "r"(EXPECT_BYTES) : "memory");
    }

    // stage U = W_hh[:, jbase..+64) as U[k][64]
    for (int i = tid; i < H_ * 16; i += NT) {
        int k = i >> 4, q = i & 15;
        *(float4*)&U[k * 64 + q * 4] =
            *(const float4*)&Whh[(size_t)k * H_ + jbase + q * 4];
    }
    // stage Wxs = W_xh[:, jbase..+64)
    for (int i = tid; i < I_ * 16; i += NT) {
        int k = i >> 4, q = i & 15;
        *(float4*)&Wxs[k * 64 + q * 4] =
            *(const float4*)&Wxh[(size_t)k * H_ + jbase + q * 4];
    }
    __syncthreads();

    const int cg = lane & 7, rg = lane >> 3;   // col group (4 cols), row group (4 rows)

    // ===== phase 0: g_xh[cta] = x(own 16 rows) @ Wxs, layout [t][col][row] =====
    {
        const int pr  = tid & 15;          // stage: batch row
        const int pih = (tid >> 4) & 3;    // stage: i-quarter
        const int ptt = tid >> 6;          // stage: t in chunk (0..7)
        const int ptw = wid >> 1;          // compute: t in chunk
        const int pcb = (wid & 1) * 32 + cg * 4;
        const int pr0 = rg * 4;

        for (int t0 = 0; t0 < T_; t0 += 8) {
            {   // stage x_ts[t][i][r] transposed
                const float* xp = x + ((size_t)(b0 + pr) * T_ + t0 + ptt) * I_ + pih * 16;
                float4 v0 = *(const float4*)(xp);
                float4 v1 = *(const float4*)(xp + 4);
                float4 v2 = *(const float4*)(xp + 8);
                float4 v3 = *(const float4*)(xp + 12);
                float* xd = x_ts + (ptt * 64 + pih * 16) * 16 + pr;
                xd[0*16]=v0.x;  xd[1*16]=v0.y;  xd[2*16]=v0.z;  xd[3*16]=v0.w;
                xd[4*16]=v1.x;  xd[5*16]=v1.y;  xd[6*16]=v1.z;  xd[7*16]=v1.w;
                xd[8*16]=v2.x;  xd[9*16]=v2.y;  xd[10*16]=v2.z; xd[11*16]=v2.w;
                xd[12*16]=v3.x; xd[13*16]=v3.y; xd[14*16]=v3.z; xd[15*16]=v3.w;
            }
            __syncthreads();

            ull a0=0,a1=0,a2=0,a3=0,a4=0,a5=0,a6=0,a7=0;
            #pragma unroll 8
            for (int k = 0; k < I_; k++) {
                float4 w4 = *(const float4*)&Wxs[k * 64 + pcb];
                ulonglong2 h2 = *(const ulonglong2*)&x_ts[(ptw * 64 + k) * 16 + pr0];
                ull w0=dup2(w4.x), w1=dup2(w4.y), w2=dup2(w4.z), w3=dup2(w4.w);
                ffma2(a0,h2.x,w0); ffma2(a1,h2.y,w0);
                ffma2(a2,h2.x,w1); ffma2(a3,h2.y,w1);
                ffma2(a4,h2.x,w2); ffma2(a5,h2.y,w2);
                ffma2(a6,h2.x,w3); ffma2(a7,h2.y,w3);
            }
            float* gb = g_xh + ((size_t)cta * T_ + t0 + ptw) * 1024;
            float2 pA, pB;
            pA=unpack2(a0); pB=unpack2(a1);
            *(float4*)&gb[(pcb+0)*16 + pr0] = make_float4(pA.x,pA.y,pB.x,pB.y);
            pA=unpack2(a2); pB=unpack2(a3);
            *(float4*)&gb[(pcb+1)*16 + pr0] = make_float4(pA.x,pA.y,pB.x,pB.y);
            pA=unpack2(a4); pB=unpack2(a5);
            *(float4*)&gb[(pcb+2)*16 + pr0] = make_float4(pA.x,pA.y,pB.x,pB.y);
            pA=unpack2(a6); pB=unpack2(a7);
            *(float4*)&gb[(pcb+3)*16 + pr0] = make_float4(pA.x,pA.y,pB.x,pB.y);
            __syncthreads();
        }
    }

    // zero h buffer 0
    for (int i = tid; i < H_ * BC / 4; i += NT)
        ((float4*)z)[i] = make_float4(0.f, 0.f, 0.f, 0.f);
    __syncthreads();
    asm volatile("barrier.cluster.arrive.aligned;" ::: "memory");
    asm volatile("barrier.cluster.wait.aligned;" ::: "memory");

    // ===== recurrence =====
    const int s  = wid >> 1;               // k-slice 0..7 (64 k each)
    const int cbase = (wid & 1) * 32 + cg * 4;
    const int r0 = rg * 4;
    const int slot = (wid & 1) * 32 + lane;     // 0..63 within slice
    const float4 bj4 = *(const float4*)&bias[jbase + cbase];
    const float* Ub  = U + s * 64 * 64;
    const float* gxb = g_xh + (size_t)cta * T_ * 1024 + cbase * 16 + r0;

    const uint32_t slice_local = smem_u32 + OFF_Z * 4 + (uint32_t)jbase * 64;
    uint32_t dst_base = 0, rmb_base = 0;
    if (wid == 0 && lane < 7) {
        int c = (rank + 1 + lane) & 7;
        asm("mapa.shared::cluster.u32 %0, %1, %2;" : "=r"(dst_base) : "r"(slice_local), "r"(c));
        asm("mapa.shared::cluster.u32 %0, %1, %2;" : "=r"(rmb_base) : "r"(mb0), "r"(c));
    }
    const uint32_t ZBUFB = H_ * BC * 4;

    for (int t = 0; t < T_; t++) {
        const int cur = t & 1, nxt = cur ^ 1;

        if (t >= 1) {
            const uint32_t mb = cur ? mb1 : mb0;
            mbar_wait(mb, (uint32_t)(((t - 1) >> 1) & 1));
            if (tid == 0)
                asm volatile("mbarrier.arrive.expect_tx.shared.b64 _, [%0], %1;"
                             :: "r"(mb), "r"(EXPECT_BYTES) : "memory");
        }
        __syncthreads();

        float4 xh0, xh1, xh2, xh3;
        if (s == 0) {
            const float* gx = gxb + (size_t)t * 1024;
            xh0 = *(const float4*)(gx);
            xh1 = *(const float4*)(gx + 16);
            xh2 = *(const float4*)(gx + 32);
            xh3 = *(const float4*)(gx + 48);
        }

        const float* zb = z + cur * (H_ * BC) + s * 1024;
        ull a0=0,a1=0,a2=0,a3=0,a4=0,a5=0,a6=0,a7=0;
        #pragma unroll 8
        for (int i = 0; i < 64; i++) {
            float4 w4 = *(const float4*)&Ub[i * 64 + cbase];
            ulonglong2 h2 = *(const ulonglong2*)&zb[i * 16 + r0];
            ull w0=dup2(w4.x), w1=dup2(w4.y), w2=dup2(w4.z), w3=dup2(w4.w);
            ffma2(a0,h2.x,w0); ffma2(a1,h2.y,w0);
            ffma2(a2,h2.x,w1); ffma2(a3,h2.y,w1);
            ffma2(a4,h2.x,w2); ffma2(a5,h2.y,w2);
            ffma2(a6,h2.x,w3); ffma2(a7,h2.y,w3);
        }

        // 3-round tree reduction: 8 slices -> slice 0
        if (s & 1) {
            ull* w = red + (((s >> 1) * 64) + slot) * 8;
            w[0]=a0; w[1]=a1; w[2]=a2; w[3]=a3; w[4]=a4; w[5]=a5; w[6]=a6; w[7]=a7;
        }
        __syncthreads();
        if (!(s & 1)) {
            ull* r_ = red + (((s >> 1) * 64) + slot) * 8;
            a0=addf2(a0,r_[0]); a1=addf2(a1,r_[1]); a2=addf2(a2,r_[2]); a3=addf2(a3,r_[3]);
            a4=addf2(a4,r_[4]); a5=addf2(a5,r_[5]); a6=addf2(a6,r_[6]); a7=addf2(a7,r_[7]);
        }
        __syncthreads();
        if (s == 2 || s == 6) {
            ull* w = red + (((s >> 2) * 64) + slot) * 8;
            w[0]=a0; w[1]=a1; w[2]=a2; w[3]=a3; w[4]=a4; w[5]=a5; w[6]=a6; w[7]=a7;
        }
        __syncthreads();
        if (s == 0 || s == 4) {
            ull* r_ = red + (((s >> 2) * 64) + slot) * 8;
            a0=addf2(a0,r_[0]); a1=addf2(a1,r_[1]); a2=addf2(a2,r_[2]); a3=addf2(a3,r_[3]);
            a4=addf2(a4,r_[4]); a5=addf2(a5,r_[5]); a6=addf2(a6,r_[6]); a7=addf2(a7,r_[7]);
        }
        __syncthreads();
        if (s == 4) {
            ull* w = red + slot * 8;
            w[0]=a0; w[1]=a1; w[2]=a2; w[3]=a3; w[4]=a4; w[5]=a5; w[6]=a6; w[7]=a7;
        }
        __syncthreads();

        if (s == 0) {
            ull* r_ = red + slot * 8;
            a0=addf2(a0,r_[0]); a1=addf2(a1,r_[1]); a2=addf2(a2,r_[2]); a3=addf2(a3,r_[3]);
            a4=addf2(a4,r_[4]); a5=addf2(a5,r_[5]); a6=addf2(a6,r_[6]); a7=addf2(a7,r_[7]);

            // write local output slice at OWN column region: jbase + cbase + c
            float* dstl = z + nxt * (H_ * BC) + (jbase + cbase) * 16 + r0;
            float2 pA, pB; float4 o;
            pA=unpack2(a0); pB=unpack2(a1);
            o.x=tanh_ap(pA.x+xh0.x+bj4.x); o.y=tanh_ap(pA.y+xh0.y+bj4.x);
            o.z=tanh_ap(pB.x+xh0.z+bj4.x); o.w=tanh_ap(pB.y+xh0.w+bj4.x);
            *(float4*)&dstl[0 * 16] = o;
            pA=unpack2(a2); pB=unpack2(a3);
            o.x=tanh_ap(pA.x+xh1.x+bj4.y); o.y=tanh_ap(pA.y+xh1.y+bj4.y);
            o.z=tanh_ap(pB.x+xh1.z+bj4.y); o.w=tanh_ap(pB.y+xh1.w+bj4.y);
            *(float4*)&dstl[1 * 16] = o;
            pA=unpack2(a4); pB=unpack2(a5);
            o.x=tanh_ap(pA.x+xh2.x+bj4.z); o.y=tanh_ap(pA.y+xh2.y+bj4.z);
            o.z=tanh_ap(pB.x+xh2.z+bj4.z); o.w=tanh_ap(pB.y+xh2.w+bj4.z);
            *(float4*)&dstl[2 * 16] = o;
            pA=unpack2(a6); pB=unpack2(a7);
            o.x=tanh_ap(pA.x+xh3.x+bj4.w); o.y=tanh_ap(pA.y+xh3.y+bj4.w);
            o.z=tanh_ap(pB.x+xh3.z+bj4.w); o.w=tanh_ap(pB.y+xh3.w+bj4.w);
            *(float4*)&dstl[3 * 16] = o;

            asm volatile("bar.sync 1, 64;" ::: "memory");
            if (wid == 0 && lane < 7) {
                asm volatile("fence.proxy.async.shared::cta;" ::: "memory");
                const uint32_t woff = (uint32_t)nxt * ZBUFB;
                asm volatile(
                    "cp.async.bulk.shared::cluster.shared::cta.mbarrier::complete_tx::bytes "
                    "[%0], [%1], %2, [%3];"
                    :: "r"(dst_base + woff), "r"(slice_local + woff),
                       "r"(SLICE_BYTES), "r"(rmb_base + (uint32_t)nxt * 8)
                    : "memory");
            }
        }
    }

    // ===== epilogue: rank 0 computes out = h_final @ fc_w^T + fc_b =====
    if (rank == 0)
        mbar_wait(mb0, 1u);                 // 256th use of mb0 -> parity 1
    __syncthreads();
    if (rank == 0 && tid < 128) {
        const float* hf = z;                // final h in buffer 0
        const int r  = tid >> 3;
        const int sg = tid & 7;
        float p = 0.f;
        #pragma unroll 8
        for (int j = sg * 64; j < sg * 64 + 64; j++)
            p = fmaf(hf[j * 16 + r], fcw[j], p);
        p += __shfl_xor_sync(0xffffffffu, p, 4);
        p += __shfl_xor_sync(0xffffffffu, p, 2);
        p += __shfl_xor_sync(0xffffffffu, p, 1);
        if (sg == 0) out[b0 + r] = p + fcb[0];
    }
    asm volatile("barrier.cluster.arrive.aligned;" ::: "memory");
    asm volatile("barrier.cluster.wait.aligned;" ::: "memory");
}

// ================= launch =================
extern "C" void kernel_launch(void* const* d_in, const int* in_sizes, int n_in,
                              void* d_out, int out_size) {
    const float* x    = (const float*)d_in[0];
    const float* Wxh  = (const float*)d_in[1];
    const float* Whh  = (const float*)d_in[2];
    const float* bias = (const float*)d_in[3];
    const float* fcw  = (const float*)d_in[4];
    const float* fcb  = (const float*)d_in[5];
    float* out = (float*)d_out;

    const int smem = SMEM_FLOATS * 4;       // 213056 B
    cudaFuncSetAttribute(rnn_fused, cudaFuncAttributeMaxDynamicSharedMemorySize, smem);
    rnn_fused<<<NGROUP * CLUSTER, NT, smem>>>(x, Wxh, Whh, bias, fcw, fcb, out);
}

// round 10
// speedup vs baseline: 2.1941x; 1.1182x over previous
#include <cuda_runtime.h>
#include <cstdint>

#define B_  256
#define T_  512
#define I_  64
#define H_  512

#define CLUSTER 8
#define NGROUP  16
#define BC      16
#define NT      512

#define SLICE_BYTES 4096
#define STRIPE_BYTES 2048
#define EXPECT_BYTES (7 * SLICE_BYTES)

// per-CTA xh scratch: [cta][t][col(64)][row(16)]
__device__ float g_xh[(size_t)(NGROUP * CLUSTER) * T_ * 64 * BC];

typedef unsigned long long ull;

// ---------------- helpers ----------------
__device__ __forceinline__ void ffma2(ull &d, ull a, ull b) {
    asm("fma.rn.f32x2 %0, %1, %2, %0;" : "+l"(d) : "l"(a), "l"(b));
}
__device__ __forceinline__ ull addf2(ull a, ull b) {
    ull d; asm("add.rn.f32x2 %0, %1, %2;" : "=l"(d) : "l"(a), "l"(b)); return d;
}
__device__ __forceinline__ ull dup2(float w) {
    ull r; asm("mov.b64 %0, {%1, %1};" : "=l"(r) : "f"(w)); return r;
}
__device__ __forceinline__ float2 unpack2(ull v) {
    float2 r; asm("mov.b64 {%0, %1}, %2;" : "=f"(r.x), "=f"(r.y) : "l"(v)); return r;
}
__device__ __forceinline__ float tanh_ap(float x) {
    float y; asm("tanh.approx.f32 %0, %1;" : "=f"(y) : "f"(x)); return y;
}
__device__ __forceinline__ void mbar_wait(uint32_t mbar, uint32_t parity) {
    asm volatile(
        "{\n\t.reg .pred P;\n\t"
        "WL_%=:\n\t"
        "mbarrier.try_wait.parity.acquire.cta.shared::cta.b64 P, [%0], %1, 0x989680;\n\t"
        "@P bra.uni WD_%=;\n\t"
        "bra.uni WL_%=;\n\t"
        "WD_%=:\n\t}"
        :: "r"(mbar), "r"(parity) : "memory");
}

// ---------------- SMEM layout (float offsets) ----------------
#define OFF_U   0                       // [512][64] W_hh slice      (131072 B)
#define OFF_Z   (H_ * 64)               // [2][512][16] hidden       ( 65536 B)
#define OFF_RED (OFF_Z + 2 * H_ * BC)   // 7168 fl = 28 KB (7 slabs); Wxs alias
#define OFF_MB  (OFF_RED + 7168)
#define SMEM_FLOATS (OFF_MB + 16)       // 56336 fl = 225344 B

// red slab indexing: slab in 0..6, i in 0..7, slot in 0..63
#define RED(slab, i, slot) (((slab) * 8 + (i)) * 64 + (slot))

__global__ void __launch_bounds__(NT, 1) __cluster_dims__(CLUSTER, 1, 1)
rnn_fused(const float* __restrict__ x,
          const float* __restrict__ Wxh,
          const float* __restrict__ Whh,
          const float* __restrict__ bias,
          const float* __restrict__ fcw,
          const float* __restrict__ fcb,
          float* __restrict__ out) {
    extern __shared__ float sm[];
    float* U   = sm + OFF_U;
    float* z   = sm + OFF_Z;
    ull*  red  = (ull*)(sm + OFF_RED);
    float* Wxs = sm + OFF_RED;          // phase-0 alias (16 KB of red)
    float* x_ts = sm + OFF_Z;           // phase-0 alias (32 KB of z region)

    const uint32_t smem_u32 = (uint32_t)__cvta_generic_to_shared(sm);
    const uint32_t mb0 = smem_u32 + OFF_MB * 4;
    const uint32_t mb1 = mb0 + 8;

    const int tid  = threadIdx.x;
    const int cta  = blockIdx.x;
    const int rank = cta & 7;
    const int bg   = cta >> 3;
    const int jbase = rank * 64;
    const int b0 = bg * BC;
    const int wid = tid >> 5, lane = tid & 31;

    if (tid == 0) {
        asm volatile("mbarrier.init.shared.b64 [%0], 1;" :: "r"(mb0) : "memory");
        asm volatile("mbarrier.init.shared.b64 [%0], 1;" :: "r"(mb1) : "memory");
        asm volatile("mbarrier.arrive.expect_tx.shared.b64 _, [%0], %1;"
                     :: "r"(mb0), "r"(EXPECT_BYTES) : "memory");
        asm volatile("mbarrier.arrive.expect_tx.shared.b64 _, [%0], %1;"
                     :: "r"(mb1), "r"(EXPECT_BYTES) : "memory");
    }

    // stage U = W_hh[:, jbase..+64) as U[k][64]
    for (int i = tid; i < H_ * 16; i += NT) {
        int k = i >> 4, q = i & 15;
        *(float4*)&U[k * 64 + q * 4] =
            *(const float4*)&Whh[(size_t)k * H_ + jbase + q * 4];
    }
    // stage Wxs = W_xh[:, jbase..+64)
    for (int i = tid; i < I_ * 16; i += NT) {
        int k = i >> 4, q = i & 15;
        *(float4*)&Wxs[k * 64 + q * 4] =
            *(const float4*)&Wxh[(size_t)k * H_ + jbase + q * 4];
    }
    __syncthreads();

    const int cg = lane & 7, rg = lane >> 3;   // col group (4 cols), row group (4 rows)

    // ===== phase 0: g_xh[cta] = x(own 16 rows) @ Wxs, layout [t][col][row] =====
    {
        const int pr  = tid & 15;          // stage: batch row
        const int pih = (tid >> 4) & 3;    // stage: i-quarter
        const int ptt = tid >> 6;          // stage: t in chunk (0..7)
        const int ptw = wid >> 1;          // compute: t in chunk
        const int pcb = (wid & 1) * 32 + cg * 4;
        const int pr0 = rg * 4;

        for (int t0 = 0; t0 < T_; t0 += 8) {
            {   // stage x_ts[t][i][r] transposed
                const float* xp = x + ((size_t)(b0 + pr) * T_ + t0 + ptt) * I_ + pih * 16;
                float4 v0 = *(const float4*)(xp);
                float4 v1 = *(const float4*)(xp + 4);
                float4 v2 = *(const float4*)(xp + 8);
                float4 v3 = *(const float4*)(xp + 12);
                float* xd = x_ts + (ptt * 64 + pih * 16) * 16 + pr;
                xd[0*16]=v0.x;  xd[1*16]=v0.y;  xd[2*16]=v0.z;  xd[3*16]=v0.w;
                xd[4*16]=v1.x;  xd[5*16]=v1.y;  xd[6*16]=v1.z;  xd[7*16]=v1.w;
                xd[8*16]=v2.x;  xd[9*16]=v2.y;  xd[10*16]=v2.z; xd[11*16]=v2.w;
                xd[12*16]=v3.x; xd[13*16]=v3.y; xd[14*16]=v3.z; xd[15*16]=v3.w;
            }
            __syncthreads();

            ull a0=0,a1=0,a2=0,a3=0,a4=0,a5=0,a6=0,a7=0;
            #pragma unroll 8
            for (int k = 0; k < I_; k++) {
                float4 w4 = *(const float4*)&Wxs[k * 64 + pcb];
                ulonglong2 h2 = *(const ulonglong2*)&x_ts[(ptw * 64 + k) * 16 + pr0];
                ull w0=dup2(w4.x), w1=dup2(w4.y), w2=dup2(w4.z), w3=dup2(w4.w);
                ffma2(a0,h2.x,w0); ffma2(a1,h2.y,w0);
                ffma2(a2,h2.x,w1); ffma2(a3,h2.y,w1);
                ffma2(a4,h2.x,w2); ffma2(a5,h2.y,w2);
                ffma2(a6,h2.x,w3); ffma2(a7,h2.y,w3);
            }
            float* gb = g_xh + ((size_t)cta * T_ + t0 + ptw) * 1024;
            float2 pA, pB;
            pA=unpack2(a0); pB=unpack2(a1);
            *(float4*)&gb[(pcb+0)*16 + pr0] = make_float4(pA.x,pA.y,pB.x,pB.y);
            pA=unpack2(a2); pB=unpack2(a3);
            *(float4*)&gb[(pcb+1)*16 + pr0] = make_float4(pA.x,pA.y,pB.x,pB.y);
            pA=unpack2(a4); pB=unpack2(a5);
            *(float4*)&gb[(pcb+2)*16 + pr0] = make_float4(pA.x,pA.y,pB.x,pB.y);
            pA=unpack2(a6); pB=unpack2(a7);
            *(float4*)&gb[(pcb+3)*16 + pr0] = make_float4(pA.x,pA.y,pB.x,pB.y);
            __syncthreads();
        }
    }

    // zero h buffer 0
    for (int i = tid; i < H_ * BC / 4; i += NT)
        ((float4*)z)[i] = make_float4(0.f, 0.f, 0.f, 0.f);
    __syncthreads();
    asm volatile("barrier.cluster.arrive.aligned;" ::: "memory");
    asm volatile("barrier.cluster.wait.aligned;" ::: "memory");

    // ===== recurrence =====
    const int s  = wid >> 1;               // k-slice 0..7 (64 k each)
    const int ch = wid & 1;                // col half
    const int cbase = ch * 32 + cg * 4;
    const int r0 = rg * 4;
    const int slot = ch * 32 + lane;       // 0..63 within slice
    const float4 bj4 = *(const float4*)&bias[jbase + cbase];
    const float* Ub  = U + s * 64 * 64;
    const float* gxb = g_xh + (size_t)cta * T_ * 1024 + cbase * 16 + r0;

    // per-warp (wid 0/1) copy descriptors: stripe = 32 cols x 16 rows = 2 KB
    const uint32_t stripe_local = smem_u32 + OFF_Z * 4
                                + (uint32_t)(jbase + ch * 32) * 64;
    uint32_t dst_base = 0, rmb_base = 0;
    if (wid < 2 && lane < 7) {
        int c = (rank + 1 + lane) & 7;
        asm("mapa.shared::cluster.u32 %0, %1, %2;" : "=r"(dst_base) : "r"(stripe_local), "r"(c));
        asm("mapa.shared::cluster.u32 %0, %1, %2;" : "=r"(rmb_base) : "r"(mb0), "r"(c));
    }
    const uint32_t ZBUFB = H_ * BC * 4;

    for (int t = 0; t < T_; t++) {
        const int cur = t & 1, nxt = cur ^ 1;

        // leader-only mbar wait; everyone else sleeps at the __syncthreads
        if (t >= 1 && wid == 0) {
            const uint32_t mb = cur ? mb1 : mb0;
            mbar_wait(mb, (uint32_t)(((t - 1) >> 1) & 1));
            if (lane == 0)
                asm volatile("mbarrier.arrive.expect_tx.shared.b64 _, [%0], %1;"
                             :: "r"(mb), "r"(EXPECT_BYTES) : "memory");
        }
        __syncthreads();

        float4 xh0, xh1, xh2, xh3;
        if (s == 0) {
            const float* gx = gxb + (size_t)t * 1024;
            xh0 = *(const float4*)(gx);
            xh1 = *(const float4*)(gx + 16);
            xh2 = *(const float4*)(gx + 32);
            xh3 = *(const float4*)(gx + 48);
        }

        const float* zb = z + cur * (H_ * BC) + s * 1024;
        ull a0=0,a1=0,a2=0,a3=0,a4=0,a5=0,a6=0,a7=0;
        #pragma unroll 8
        for (int i = 0; i < 64; i++) {
            float4 w4 = *(const float4*)&Ub[i * 64 + cbase];
            ulonglong2 h2 = *(const ulonglong2*)&zb[i * 16 + r0];
            ull w0=dup2(w4.x), w1=dup2(w4.y), w2=dup2(w4.z), w3=dup2(w4.w);
            ffma2(a0,h2.x,w0); ffma2(a1,h2.y,w0);
            ffma2(a2,h2.x,w1); ffma2(a3,h2.y,w1);
            ffma2(a4,h2.x,w2); ffma2(a5,h2.y,w2);
            ffma2(a6,h2.x,w3); ffma2(a7,h2.y,w3);
        }

        // ===== 2-round reduction: 8 slices -> slice 0 =====
        // round A: s4..s7 -> slabs 0..3
        if (s >= 4) {
            ull* w = red;
            int slab = s - 4;
            w[RED(slab,0,slot)]=a0; w[RED(slab,1,slot)]=a1;
            w[RED(slab,2,slot)]=a2; w[RED(slab,3,slot)]=a3;
            w[RED(slab,4,slot)]=a4; w[RED(slab,5,slot)]=a5;
            w[RED(slab,6,slot)]=a6; w[RED(slab,7,slot)]=a7;
        }
        __syncthreads();
        if (s < 4) {
            const ull* r_ = red;
            int slab = s;
            a0=addf2(a0,r_[RED(slab,0,slot)]); a1=addf2(a1,r_[RED(slab,1,slot)]);
            a2=addf2(a2,r_[RED(slab,2,slot)]); a3=addf2(a3,r_[RED(slab,3,slot)]);
            a4=addf2(a4,r_[RED(slab,4,slot)]); a5=addf2(a5,r_[RED(slab,5,slot)]);
            a6=addf2(a6,r_[RED(slab,6,slot)]); a7=addf2(a7,r_[RED(slab,7,slot)]);
        }
        // round B: s1..s3 -> slabs 4..6
        if (s >= 1 && s <= 3) {
            ull* w = red;
            int slab = 3 + s;
            w[RED(slab,0,slot)]=a0; w[RED(slab,1,slot)]=a1;
            w[RED(slab,2,slot)]=a2; w[RED(slab,3,slot)]=a3;
            w[RED(slab,4,slot)]=a4; w[RED(slab,5,slot)]=a5;
            w[RED(slab,6,slot)]=a6; w[RED(slab,7,slot)]=a7;
        }
        __syncthreads();

        if (s == 0) {
            const ull* r_ = red;
            #pragma unroll
            for (int slab = 4; slab <= 6; slab++) {
                a0=addf2(a0,r_[RED(slab,0,slot)]); a1=addf2(a1,r_[RED(slab,1,slot)]);
                a2=addf2(a2,r_[RED(slab,2,slot)]); a3=addf2(a3,r_[RED(slab,3,slot)]);
                a4=addf2(a4,r_[RED(slab,4,slot)]); a5=addf2(a5,r_[RED(slab,5,slot)]);
                a6=addf2(a6,r_[RED(slab,6,slot)]); a7=addf2(a7,r_[RED(slab,7,slot)]);
            }

            // write local output slice at OWN column region
            float* dstl = z + nxt * (H_ * BC) + (jbase + cbase) * 16 + r0;
            float2 pA, pB; float4 o;
            pA=unpack2(a0); pB=unpack2(a1);
            o.x=tanh_ap(pA.x+xh0.x+bj4.x); o.y=tanh_ap(pA.y+xh0.y+bj4.x);
            o.z=tanh_ap(pB.x+xh0.z+bj4.x); o.w=tanh_ap(pB.y+xh0.w+bj4.x);
            *(float4*)&dstl[0 * 16] = o;
            pA=unpack2(a2); pB=unpack2(a3);
            o.x=tanh_ap(pA.x+xh1.x+bj4.y); o.y=tanh_ap(pA.y+xh1.y+bj4.y);
            o.z=tanh_ap(pB.x+xh1.z+bj4.y); o.w=tanh_ap(pB.y+xh1.w+bj4.y);
            *(float4*)&dstl[1 * 16] = o;
            pA=unpack2(a4); pB=unpack2(a5);
            o.x=tanh_ap(pA.x+xh2.x+bj4.z); o.y=tanh_ap(pA.y+xh2.y+bj4.z);
            o.z=tanh_ap(pB.x+xh2.z+bj4.z); o.w=tanh_ap(pB.y+xh2.w+bj4.z);
            *(float4*)&dstl[2 * 16] = o;
            pA=unpack2(a6); pB=unpack2(a7);
            o.x=tanh_ap(pA.x+xh3.x+bj4.w); o.y=tanh_ap(pA.y+xh3.y+bj4.w);
            o.z=tanh_ap(pB.x+xh3.z+bj4.w); o.w=tanh_ap(pB.y+xh3.w+bj4.w);
            *(float4*)&dstl[3 * 16] = o;

            // each s0 warp pushes its own 2 KB stripe to the 7 peers
            __syncwarp();
            if (lane < 7) {
                asm volatile("fence.proxy.async.shared::cta;" ::: "memory");
                const uint32_t woff = (uint32_t)nxt * ZBUFB;
                asm volatile(
                    "cp.async.bulk.shared::cluster.shared::cta.mbarrier::complete_tx::bytes "
                    "[%0], [%1], %2, [%3];"
                    :: "r"(dst_base + woff), "r"(stripe_local + woff),
                       "r"(STRIPE_BYTES), "r"(rmb_base + (uint32_t)nxt * 8)
                    : "memory");
            }
        }
    }

    // ===== epilogue: rank 0 computes out = h_final @ fc_w^T + fc_b =====
    if (rank == 0 && wid == 0)
        mbar_wait(mb0, 1u);                 // 256th use of mb0 -> parity 1
    __syncthreads();
    if (rank == 0 && tid < 128) {
        const float* hf = z;                // final h in buffer 0
        const int r  = tid >> 3;
        const int sg = tid & 7;
        float p = 0.f;
        #pragma unroll 8
        for (int j = sg * 64; j < sg * 64 + 64; j++)
            p = fmaf(hf[j * 16 + r], fcw[j], p);
        p += __shfl_xor_sync(0xffffffffu, p, 4);
        p += __shfl_xor_sync(0xffffffffu, p, 2);
        p += __shfl_xor_sync(0xffffffffu, p, 1);
        if (sg == 0) out[b0 + r] = p + fcb[0];
    }
    asm volatile("barrier.cluster.arrive.aligned;" ::: "memory");
    asm volatile("barrier.cluster.wait.aligned;" ::: "memory");
}

// ================= launch =================
extern "C" void kernel_launch(void* const* d_in, const int* in_sizes, int n_in,
                              void* d_out, int out_size) {
    const float* x    = (const float*)d_in[0];
    const float* Wxh  = (const float*)d_in[1];
    const float* Whh  = (const float*)d_in[2];
    const float* bias = (const float*)d_in[3];
    const float* fcw  = (const float*)d_in[4];
    const float* fcb  = (const float*)d_in[5];
    float* out = (float*)d_out;

    const int smem = SMEM_FLOATS * 4;       // 225344 B
    cudaFuncSetAttribute(rnn_fused, cudaFuncAttributeMaxDynamicSharedMemorySize, smem);
    rnn_fused<<<NGROUP * CLUSTER, NT, smem>>>(x, Wxh, Whh, bias, fcw, fcb, out);
}

// round 11
// speedup vs baseline: 2.2815x; 1.0398x over previous
#include <cuda_runtime.h>
#include <cstdint>

#define B_  256
#define T_  512
#define I_  64
#define H_  512

#define CLUSTER 8
#define NGROUP  16
#define BC      16
#define NT      1024

#define STRIPE_BYTES 2048
#define SRC_EXPECT   4096        // 2 stripes per source per step

// per-CTA xh scratch: [cta][t][col(64)][row(16)]
__device__ float g_xh[(size_t)(NGROUP * CLUSTER) * T_ * 64 * BC];

typedef unsigned long long ull;

// ---------------- helpers ----------------
__device__ __forceinline__ void ffma2(ull &d, ull a, ull b) {
    asm("fma.rn.f32x2 %0, %1, %2, %0;" : "+l"(d) : "l"(a), "l"(b));
}
__device__ __forceinline__ ull addf2(ull a, ull b) {
    ull d; asm("add.rn.f32x2 %0, %1, %2;" : "=l"(d) : "l"(a), "l"(b)); return d;
}
__device__ __forceinline__ ull dup2(float w) {
    ull r; asm("mov.b64 %0, {%1, %1};" : "=l"(r) : "f"(w)); return r;
}
__device__ __forceinline__ float2 unpack2(ull v) {
    float2 r; asm("mov.b64 {%0, %1}, %2;" : "=f"(r.x), "=f"(r.y) : "l"(v)); return r;
}
__device__ __forceinline__ float tanh_ap(float x) {
    float y; asm("tanh.approx.f32 %0, %1;" : "=f"(y) : "f"(x)); return y;
}
__device__ __forceinline__ void mbar_wait(uint32_t mbar, uint32_t parity) {
    asm volatile(
        "{\n\t.reg .pred P;\n\t"
        "WL_%=:\n\t"
        "mbarrier.try_wait.parity.acquire.cta.shared::cta.b64 P, [%0], %1, 0x989680;\n\t"
        "@P bra.uni WD_%=;\n\t"
        "bra.uni WL_%=;\n\t"
        "WD_%=:\n\t}"
        :: "r"(mbar), "r"(parity) : "memory");
}

// ---------------- SMEM layout (float offsets) ----------------
#define OFF_U   0                       // [512][64] W_hh slice      (131072 B)
#define OFF_Z   (H_ * 64)               // [2][512][16] hidden       ( 65536 B)
#define OFF_RED (OFF_Z + 2 * H_ * BC)   // 8192 fl = 32 KB, 8 slabs; Wxs alias
#define OFF_MB  (OFF_RED + 8192)        // 16 mbars (128 B)
#define SMEM_FLOATS (OFF_MB + 32)       // 57376 fl = 229504 B

// slab: 0..7, i: 0..7, slot: 0..63
#define RED(slab, i, slot) (((slab) * 8 + (i)) * 64 + (slot))

__global__ void __launch_bounds__(NT, 1) __cluster_dims__(CLUSTER, 1, 1)
rnn_fused(const float* __restrict__ x,
          const float* __restrict__ Wxh,
          const float* __restrict__ Whh,
          const float* __restrict__ bias,
          const float* __restrict__ fcw,
          const float* __restrict__ fcb,
          float* __restrict__ out) {
    extern __shared__ float sm[];
    float* U   = sm + OFF_U;
    float* z   = sm + OFF_Z;
    ull*  red  = (ull*)(sm + OFF_RED);
    float* Wxs = sm + OFF_RED;          // phase-0 alias
    float* x_ts = sm + OFF_Z;           // phase-0 alias (64 KB = z region)

    const uint32_t smem_u32 = (uint32_t)__cvta_generic_to_shared(sm);
    const uint32_t mb_base = smem_u32 + OFF_MB * 4;   // mbar[buf*8+src]

    const int tid  = threadIdx.x;
    const int cta  = blockIdx.x;
    const int rank = cta & 7;
    const int bg   = cta >> 3;
    const int jbase = rank * 64;
    const int b0 = bg * BC;
    const int wid = tid >> 5, lane = tid & 31;

    // init 16 mbars; pre-arm the 14 used (src != rank)
    if (tid < 16) {
        asm volatile("mbarrier.init.shared.b64 [%0], 1;"
                     :: "r"(mb_base + tid * 8) : "memory");
    }
    __syncthreads();
    if (tid < 16 && (tid & 7) != rank) {
        asm volatile("mbarrier.arrive.expect_tx.shared.b64 _, [%0], %1;"
                     :: "r"(mb_base + tid * 8), "r"(SRC_EXPECT) : "memory");
    }

    // stage U = W_hh[:, jbase..+64) as U[k][64]
    for (int i = tid; i < H_ * 16; i += NT) {
        int k = i >> 4, q = i & 15;
        *(float4*)&U[k * 64 + q * 4] =
            *(const float4*)&Whh[(size_t)k * H_ + jbase + q * 4];
    }
    // stage Wxs
    for (int i = tid; i < I_ * 16; i += NT) {
        int k = i >> 4, q = i & 15;
        *(float4*)&Wxs[k * 64 + q * 4] =
            *(const float4*)&Wxh[(size_t)k * H_ + jbase + q * 4];
    }
    __syncthreads();

    const int cg = lane & 7, rg = lane >> 3;

    // ===== phase 0: g_xh[cta] = x(own 16 rows) @ Wxs, layout [t][col][row] =====
    {
        const int pr  = tid & 15;          // stage: batch row
        const int pih = (tid >> 4) & 3;    // stage: i-quarter
        const int ptt = tid >> 6;          // stage: t in chunk (0..15)
        const int ptw = wid >> 1;          // compute: t in chunk (0..15)
        const int pcb = (wid & 1) * 32 + cg * 4;
        const int pr0 = rg * 4;

        for (int t0 = 0; t0 < T_; t0 += 16) {
            {   // stage x_ts[t][i][r] transposed (16 t x 64 i x 16 r = 64 KB)
                const float* xp = x + ((size_t)(b0 + pr) * T_ + t0 + ptt) * I_ + pih * 16;
                float4 v0 = *(const float4*)(xp);
                float4 v1 = *(const float4*)(xp + 4);
                float4 v2 = *(const float4*)(xp + 8);
                float4 v3 = *(const float4*)(xp + 12);
                float* xd = x_ts + (ptt * 64 + pih * 16) * 16 + pr;
                xd[0*16]=v0.x;  xd[1*16]=v0.y;  xd[2*16]=v0.z;  xd[3*16]=v0.w;
                xd[4*16]=v1.x;  xd[5*16]=v1.y;  xd[6*16]=v1.z;  xd[7*16]=v1.w;
                xd[8*16]=v2.x;  xd[9*16]=v2.y;  xd[10*16]=v2.z; xd[11*16]=v2.w;
                xd[12*16]=v3.x; xd[13*16]=v3.y; xd[14*16]=v3.z; xd[15*16]=v3.w;
            }
            __syncthreads();

            ull a0=0,a1=0,a2=0,a3=0,a4=0,a5=0,a6=0,a7=0;
            #pragma unroll 8
            for (int k = 0; k < I_; k++) {
                float4 w4 = *(const float4*)&Wxs[k * 64 + pcb];
                ulonglong2 h2 = *(const ulonglong2*)&x_ts[(ptw * 64 + k) * 16 + pr0];
                ull w0=dup2(w4.x), w1=dup2(w4.y), w2=dup2(w4.z), w3=dup2(w4.w);
                ffma2(a0,h2.x,w0); ffma2(a1,h2.y,w0);
                ffma2(a2,h2.x,w1); ffma2(a3,h2.y,w1);
                ffma2(a4,h2.x,w2); ffma2(a5,h2.y,w2);
                ffma2(a6,h2.x,w3); ffma2(a7,h2.y,w3);
            }
            float* gb = g_xh + ((size_t)cta * T_ + t0 + ptw) * 1024;
            float2 pA, pB;
            pA=unpack2(a0); pB=unpack2(a1);
            *(float4*)&gb[(pcb+0)*16 + pr0] = make_float4(pA.x,pA.y,pB.x,pB.y);
            pA=unpack2(a2); pB=unpack2(a3);
            *(float4*)&gb[(pcb+1)*16 + pr0] = make_float4(pA.x,pA.y,pB.x,pB.y);
            pA=unpack2(a4); pB=unpack2(a5);
            *(float4*)&gb[(pcb+2)*16 + pr0] = make_float4(pA.x,pA.y,pB.x,pB.y);
            pA=unpack2(a6); pB=unpack2(a7);
            *(float4*)&gb[(pcb+3)*16 + pr0] = make_float4(pA.x,pA.y,pB.x,pB.y);
            __syncthreads();
        }
    }

    // zero h buffer 0 (and buffer 1 region is overwritten before first read)
    for (int i = tid; i < H_ * BC / 4; i += NT)
        ((float4*)z)[i] = make_float4(0.f, 0.f, 0.f, 0.f);
    __syncthreads();
    asm volatile("barrier.cluster.arrive.aligned;" ::: "memory");
    asm volatile("barrier.cluster.wait.aligned;" ::: "memory");

    // ===== recurrence =====
    const int s  = wid >> 1;                   // 0..15
    const int ch = wid & 1;
    const int l  = (rank * 2 + s) & 15;        // logical k-slice (32 k's)
    const int src = (rank + (s >> 1)) & 7;     // source CTA of this slice
    const bool needwait = (s >= 2);
    const bool isS1 = (wid == 2 || wid == 3);
    const int cbase = ch * 32 + cg * 4;
    const int r0 = rg * 4;
    const int slot = ch * 32 + lane;           // 0..63
    const int zoff = l * 32 * 16;
    const float* Ub = U + l * 32 * 64;
    const float* gxb = g_xh + (size_t)cta * T_ * 1024 + cbase * 16 + r0;
    const float4 bj4 = *(const float4*)&bias[jbase + cbase];

    const uint32_t stripe_local = smem_u32 + OFF_Z * 4
                                + (uint32_t)(jbase + ch * 32) * 64;
    uint32_t dst_base = 0, rmb_map = 0;
    if (wid < 2 && lane < 7) {
        int c = (rank + 1 + lane) & 7;
        asm("mapa.shared::cluster.u32 %0, %1, %2;" : "=r"(dst_base) : "r"(stripe_local), "r"(c));
        asm("mapa.shared::cluster.u32 %0, %1, %2;" : "=r"(rmb_map) : "r"(mb_base), "r"(c));
    }
    const uint32_t ZBUFB = H_ * BC * 4;
    uint32_t par0 = 0, par1 = 0;

    for (int t = 0; t < T_; t++) {
        const int cur = t & 1, nxt = cur ^ 1;

        if (t >= 1) {
            if (needwait) {
                const uint32_t mb = mb_base + (uint32_t)(cur * 8 + src) * 8;
                mbar_wait(mb, cur ? par1 : par0);
                if (!(s & 1) && ch == 0 && lane == 0)
                    asm volatile("mbarrier.arrive.expect_tx.shared.b64 _, [%0], %1;"
                                 :: "r"(mb), "r"(SRC_EXPECT) : "memory");
                if (cur) par1 ^= 1; else par0 ^= 1;
            } else if (isS1) {
                asm volatile("bar.sync 1, 128;" ::: "memory");
            }
        }

        const float* zb = z + cur * (H_ * BC) + zoff;
        ull a0=0,a1=0,a2=0,a3=0,a4=0,a5=0,a6=0,a7=0;
        #pragma unroll 8
        for (int i = 0; i < 32; i++) {
            float4 w4 = *(const float4*)&Ub[i * 64 + cbase];
            ulonglong2 h2 = *(const ulonglong2*)&zb[i * 16 + r0];
            ull w0=dup2(w4.x), w1=dup2(w4.y), w2=dup2(w4.z), w3=dup2(w4.w);
            ffma2(a0,h2.x,w0); ffma2(a1,h2.y,w0);
            ffma2(a2,h2.x,w1); ffma2(a3,h2.y,w1);
            ffma2(a4,h2.x,w2); ffma2(a5,h2.y,w2);
            ffma2(a6,h2.x,w3); ffma2(a7,h2.y,w3);
        }

        // producers prefetch xh (latency covered by the reduction rounds)
        float4 xh0, xh1, xh2, xh3;
        if (wid < 2) {
            const float* gx = gxb + (size_t)t * 1024;
            xh0 = *(const float4*)(gx);
            xh1 = *(const float4*)(gx + 16);
            xh2 = *(const float4*)(gx + 32);
            xh3 = *(const float4*)(gx + 48);
        }

        // ===== reduction 16 -> 1 (4 syncthreads) =====
        if (s & 1) {                        // R1 write: odd s -> slab s>>1
            ull* w = red; int slab = s >> 1;
            w[RED(slab,0,slot)]=a0; w[RED(slab,1,slot)]=a1;
            w[RED(slab,2,slot)]=a2; w[RED(slab,3,slot)]=a3;
            w[RED(slab,4,slot)]=a4; w[RED(slab,5,slot)]=a5;
            w[RED(slab,6,slot)]=a6; w[RED(slab,7,slot)]=a7;
        }
        __syncthreads();                    // sync1
        if (!(s & 1)) {                     // R1 add: even s
            const ull* r_ = red; int slab = s >> 1;
            a0=addf2(a0,r_[RED(slab,0,slot)]); a1=addf2(a1,r_[RED(slab,1,slot)]);
            a2=addf2(a2,r_[RED(slab,2,slot)]); a3=addf2(a3,r_[RED(slab,3,slot)]);
            a4=addf2(a4,r_[RED(slab,4,slot)]); a5=addf2(a5,r_[RED(slab,5,slot)]);
            a6=addf2(a6,r_[RED(slab,6,slot)]); a7=addf2(a7,r_[RED(slab,7,slot)]);
        }
        __syncthreads();                    // sync2
        if (!(s & 1) && (s >> 1) >= 4) {    // R2 write: q4..7 -> slabs 0..3
            ull* w = red; int slab = (s >> 1) - 4;
            w[RED(slab,0,slot)]=a0; w[RED(slab,1,slot)]=a1;
            w[RED(slab,2,slot)]=a2; w[RED(slab,3,slot)]=a3;
            w[RED(slab,4,slot)]=a4; w[RED(slab,5,slot)]=a5;
            w[RED(slab,6,slot)]=a6; w[RED(slab,7,slot)]=a7;
        }
        __syncthreads();                    // sync3
        if (!(s & 1) && (s >> 1) < 4) {     // R2 add: q0..3
            const ull* r_ = red; int slab = s >> 1;
            a0=addf2(a0,r_[RED(slab,0,slot)]); a1=addf2(a1,r_[RED(slab,1,slot)]);
            a2=addf2(a2,r_[RED(slab,2,slot)]); a3=addf2(a3,r_[RED(slab,3,slot)]);
            a4=addf2(a4,r_[RED(slab,4,slot)]); a5=addf2(a5,r_[RED(slab,5,slot)]);
            a6=addf2(a6,r_[RED(slab,6,slot)]); a7=addf2(a7,r_[RED(slab,7,slot)]);
            int q = s >> 1;
            if (q >= 1) {                   // R3 write: q1..3 -> slabs 4..6
                ull* w = red; int slab = 3 + q;
                w[RED(slab,0,slot)]=a0; w[RED(slab,1,slot)]=a1;
                w[RED(slab,2,slot)]=a2; w[RED(slab,3,slot)]=a3;
                w[RED(slab,4,slot)]=a4; w[RED(slab,5,slot)]=a5;
                w[RED(slab,6,slot)]=a6; w[RED(slab,7,slot)]=a7;
            }
        }
        __syncthreads();                    // sync4

        if (wid < 2) {                      // q0: final adds + epilogue + push
            const ull* r_ = red;
            #pragma unroll
            for (int slab = 4; slab <= 6; slab++) {
                a0=addf2(a0,r_[RED(slab,0,slot)]); a1=addf2(a1,r_[RED(slab,1,slot)]);
                a2=addf2(a2,r_[RED(slab,2,slot)]); a3=addf2(a3,r_[RED(slab,3,slot)]);
                a4=addf2(a4,r_[RED(slab,4,slot)]); a5=addf2(a5,r_[RED(slab,5,slot)]);
                a6=addf2(a6,r_[RED(slab,6,slot)]); a7=addf2(a7,r_[RED(slab,7,slot)]);
            }

            float* dstl = z + nxt * (H_ * BC) + (jbase + cbase) * 16 + r0;
            float2 pA, pB; float4 o;
            pA=unpack2(a0); pB=unpack2(a1);
            o.x=tanh_ap(pA.x+xh0.x+bj4.x); o.y=tanh_ap(pA.y+xh0.y+bj4.x);
            o.z=tanh_ap(pB.x+xh0.z+bj4.x); o.w=tanh_ap(pB.y+xh0.w+bj4.x);
            *(float4*)&dstl[0 * 16] = o;
            pA=unpack2(a2); pB=unpack2(a3);
            o.x=tanh_ap(pA.x+xh1.x+bj4.y); o.y=tanh_ap(pA.y+xh1.y+bj4.y);
            o.z=tanh_ap(pB.x+xh1.z+bj4.y); o.w=tanh_ap(pB.y+xh1.w+bj4.y);
            *(float4*)&dstl[1 * 16] = o;
            pA=unpack2(a4); pB=unpack2(a5);
            o.x=tanh_ap(pA.x+xh2.x+bj4.z); o.y=tanh_ap(pA.y+xh2.y+bj4.z);
            o.z=tanh_ap(pB.x+xh2.z+bj4.z); o.w=tanh_ap(pB.y+xh2.w+bj4.z);
            *(float4*)&dstl[2 * 16] = o;
            pA=unpack2(a6); pB=unpack2(a7);
            o.x=tanh_ap(pA.x+xh3.x+bj4.w); o.y=tanh_ap(pA.y+xh3.y+bj4.w);
            o.z=tanh_ap(pB.x+xh3.z+bj4.w); o.w=tanh_ap(pB.y+xh3.w+bj4.w);
            *(float4*)&dstl[3 * 16] = o;

            __syncwarp();
            asm volatile("bar.sync 1, 128;" ::: "memory");   // pairs with s1 @ t+1
            if (lane < 7) {
                asm volatile("fence.proxy.async.shared::cta;" ::: "memory");
                const uint32_t woff = (uint32_t)nxt * ZBUFB;
                asm volatile(
                    "cp.async.bulk.shared::cluster.shared::cta.mbarrier::complete_tx::bytes "
                    "[%0], [%1], %2, [%3];"
                    :: "r"(dst_base + woff), "r"(stripe_local + woff),
                       "r"(STRIPE_BYTES),
                       "r"(rmb_map + (uint32_t)(nxt * 8 + rank) * 8)
                    : "memory");
            }
        }
    }

    // final drains: every waiting warp absorbs the t=511 push (buffer 0)
    if (needwait) {
        mbar_wait(mb_base + (uint32_t)src * 8, par0);
    } else if (isS1) {
        asm volatile("bar.sync 1, 128;" ::: "memory");
    }
    __syncthreads();

    // ===== epilogue: rank 0 computes out = h_final @ fc_w^T + fc_b =====
    if (rank == 0 && tid < 128) {
        const float* hf = z;                // final h in buffer 0
        const int r  = tid >> 3;
        const int sg = tid & 7;
        float p = 0.f;
        #pragma unroll 8
        for (int j = sg * 64; j < sg * 64 + 64; j++)
            p = fmaf(hf[j * 16 + r], fcw[j], p);
        p += __shfl_xor_sync(0xffffffffu, p, 4);
        p += __shfl_xor_sync(0xffffffffu, p, 2);
        p += __shfl_xor_sync(0xffffffffu, p, 1);
        if (sg == 0) out[b0 + r] = p + fcb[0];
    }
    asm volatile("barrier.cluster.arrive.aligned;" ::: "memory");
    asm volatile("barrier.cluster.wait.aligned;" ::: "memory");
}

// ================= launch =================
extern "C" void kernel_launch(void* const* d_in, const int* in_sizes, int n_in,
                              void* d_out, int out_size) {
    const float* x    = (const float*)d_in[0];
    const float* Wxh  = (const float*)d_in[1];
    const float* Whh  = (const float*)d_in[2];
    const float* bias = (const float*)d_in[3];
    const float* fcw  = (const float*)d_in[4];
    const float* fcb  = (const float*)d_in[5];
    float* out = (float*)d_out;

    const int smem = SMEM_FLOATS * 4;       // 229504 B
    cudaFuncSetAttribute(rnn_fused, cudaFuncAttributeMaxDynamicSharedMemorySize, smem);
    rnn_fused<<<NGROUP * CLUSTER, NT, smem>>>(x, Wxh, Whh, bias, fcw, fcb, out);
}